// round 4
// baseline (speedup 1.0000x reference)
#include <cuda_runtime.h>
#include <cuda_bf16.h>

// Problem constants (fixed shapes)
#define NND   50000
#define NE    800000
#define NET   850000      // E + N self loops
#define FIN   500
#define H1    8
#define C1    16
#define HC    128         // H1*C1
#define HCV   32          // HC/4 float4s per node
#define NCLS  7
#define NEG   0.2f

// ---------------- scratch (static device globals; no allocs) ----------------
__device__ float4 g_h1v[NND * HCV];    // layer1 features h = x@W1 (vec4)
__device__ float  g_asrc1[NND * H1];
__device__ float  g_adst1[NND * H1];
__device__ float4 g_h2v[NND * HCV];    // relu(agg1 + b1) (vec4)
__device__ float  g_p2[NND * NCLS];    // layer2 projected
__device__ float  g_a2s[NND];
__device__ float  g_a2d[NND];
__device__ int    g_deg[NND];
__device__ int    g_offs[NND];
__device__ int    g_cur[NND];
__device__ int    g_csrc[NET];         // CSR: sources of incoming edges per dst
__device__ int    g_is64;              // 1 if edge_index is int64, 0 if int32

// ---------------- dtype detection ----------------
// For int64 edge data (values < 2^31), every odd 32-bit word is the zero high
// half. For int32 data, odd words are real node ids (random in [0,50000)).
__global__ __launch_bounds__(256) void k_detect(const unsigned int* __restrict__ w) {
    __shared__ unsigned int s[256];
    unsigned int v = 0;
    for (int i = threadIdx.x; i < 8192; i += 256) v |= w[2 * i + 1];
    s[threadIdx.x] = v;
    __syncthreads();
    for (int off = 128; off > 0; off >>= 1) {
        if (threadIdx.x < off) s[threadIdx.x] |= s[threadIdx.x + off];
        __syncthreads();
    }
    if (threadIdx.x == 0) g_is64 = (s[0] == 0u) ? 1 : 0;
}

__device__ __forceinline__ int load_edge(const void* ei, long long idx) {
    if (g_is64) return (int)((const long long*)ei)[idx];
    return ((const int*)ei)[idx];
}

// ---------------- CSR build ----------------
__global__ __launch_bounds__(256) void k_zero_deg() {
    int i = blockIdx.x * blockDim.x + threadIdx.x;
    if (i < NND) g_deg[i] = 0;
}

__global__ __launch_bounds__(256) void k_hist(const void* __restrict__ ei) {
    int e = blockIdx.x * blockDim.x + threadIdx.x;
    if (e >= NET) return;
    int dst = (e < NE) ? load_edge(ei, (long long)NE + e) : (e - NE);
    if ((unsigned)dst < NND) atomicAdd(&g_deg[dst], 1);
}

__global__ __launch_bounds__(1024) void k_scan() {   // single block, 1024 threads
    __shared__ int s[1024];
    const int t = threadIdx.x;
    const int CH = (NND + 1023) / 1024;   // 49
    const int base = t * CH;
    int loc = 0;
    for (int i = 0; i < CH; i++) {
        int idx = base + i;
        if (idx < NND) loc += g_deg[idx];
    }
    s[t] = loc;
    __syncthreads();
    for (int off = 1; off < 1024; off <<= 1) {
        int v = 0;
        if (t >= off) v = s[t - off];
        __syncthreads();
        s[t] += v;
        __syncthreads();
    }
    int run = s[t] - loc;   // exclusive prefix
    for (int i = 0; i < CH; i++) {
        int idx = base + i;
        if (idx < NND) {
            g_offs[idx] = run;
            g_cur[idx]  = run;
            run += g_deg[idx];
        }
    }
}

__global__ __launch_bounds__(256) void k_scatter(const void* __restrict__ ei) {
    int e = blockIdx.x * blockDim.x + threadIdx.x;
    if (e >= NET) return;
    int src, dst;
    if (e < NE) {
        src = load_edge(ei, e);
        dst = load_edge(ei, (long long)NE + e);
    } else {
        src = e - NE; dst = e - NE;
    }
    if ((unsigned)dst >= NND || (unsigned)src >= NND) return;  // defensive
    int pos = atomicAdd(&g_cur[dst], 1);
    if ((unsigned)pos < NET) g_csrc[pos] = src;
}

// ---------------- GEMM1: h1 = x @ W1   [50000,500]x[500,128] ----------------
#define BM 64
#define BK 20
__global__ __launch_bounds__(256) void k_gemm1(const float* __restrict__ x,
                                               const float* __restrict__ W1) {
    __shared__ float  As[BK][BM + 1];   // [k][m], +1 pad
    __shared__ float4 Bs[BK][HCV];      // [k][n4]
    const int tid = threadIdx.x;
    const int tx = tid & 31;       // n4 index (4 cols)
    const int ty = tid >> 5;       // row group (8 rows)
    const int rowBase = blockIdx.x * BM;

    float acc[8][4];
#pragma unroll
    for (int i = 0; i < 8; i++)
#pragma unroll
        for (int j = 0; j < 4; j++) acc[i][j] = 0.f;

    for (int k0 = 0; k0 < FIN; k0 += BK) {
        // load A tile: 64 rows x 20 k (1280 elems, 5/thread)
#pragma unroll
        for (int i = 0; i < 5; i++) {
            int idx = tid + i * 256;
            int m = idx / BK, k = idx - m * BK;
            int r = rowBase + m;
            float v = 0.f;
            if (r < NND) v = x[(long)r * FIN + k0 + k];
            As[k][m] = v;
        }
        // load B tile: 20 k x 32 float4; lower 160 threads do 4 each
        if (tid < 160) {
#pragma unroll
            for (int i = 0; i < 4; i++) {
                int e  = tid * 4 + i;   // 0..639
                int k  = e >> 5;        // /32
                int n4 = e & 31;
                float4 b;
                const float* wp = &W1[(k0 + k) * HC + n4 * 4];
                b.x = wp[0]; b.y = wp[1]; b.z = wp[2]; b.w = wp[3];
                Bs[k][n4] = b;
            }
        }
        __syncthreads();
#pragma unroll
        for (int kk = 0; kk < BK; kk++) {
            float4 b4 = Bs[kk][tx];
#pragma unroll
            for (int i = 0; i < 8; i++) {
                float a = As[kk][ty * 8 + i];
                acc[i][0] += a * b4.x;
                acc[i][1] += a * b4.y;
                acc[i][2] += a * b4.z;
                acc[i][3] += a * b4.w;
            }
        }
        __syncthreads();
    }
#pragma unroll
    for (int i = 0; i < 8; i++) {
        int r = rowBase + ty * 8 + i;
        if (r < NND) {
            g_h1v[r * HCV + tx] = make_float4(acc[i][0], acc[i][1], acc[i][2], acc[i][3]);
        }
    }
}

// ---------------- per-node attention logits layer 1 ----------------
__global__ __launch_bounds__(256) void k_att1(const float* __restrict__ att_src,
                                              const float* __restrict__ att_dst) {
    int t = blockIdx.x * blockDim.x + threadIdx.x;
    if (t >= NND * H1) return;
    int n = t / H1, h = t - n * H1;
    float ss = 0.f, sd = 0.f;
#pragma unroll
    for (int j = 0; j < 4; j++) {
        float4 v = g_h1v[n * HCV + h * 4 + j];
        ss += v.x * att_src[h * C1 + j * 4 + 0] + v.y * att_src[h * C1 + j * 4 + 1]
            + v.z * att_src[h * C1 + j * 4 + 2] + v.w * att_src[h * C1 + j * 4 + 3];
        sd += v.x * att_dst[h * C1 + j * 4 + 0] + v.y * att_dst[h * C1 + j * 4 + 1]
            + v.z * att_dst[h * C1 + j * 4 + 2] + v.w * att_dst[h * C1 + j * 4 + 3];
    }
    g_asrc1[t] = ss;
    g_adst1[t] = sd;
}

// ---------------- layer-1 aggregation (gather, softmax-normalized) ----------
// warp per dst node; lane covers one float4 (4 channels), head = lane>>2
__global__ __launch_bounds__(256) void k_agg1(const float* __restrict__ b1) {
    int warp = (blockIdx.x * blockDim.x + threadIdx.x) >> 5;
    int lane = threadIdx.x & 31;
    if (warp >= NND) return;
    const int n = warp;
    const int head = lane >> 2;

    const float ad = g_adst1[n * H1 + head];
    const int beg = g_offs[n];
    const int deg = g_deg[n];

    float4 acc = make_float4(0.f, 0.f, 0.f, 0.f);
    float den = 0.f;
    for (int t = 0; t < deg; t++) {
        int src = g_csrc[beg + t];                 // same addr across warp
        float e = g_asrc1[src * H1 + head] + ad;
        e = (e > 0.f) ? e : NEG * e;
        float w = __expf(e);
        float4 hv = g_h1v[src * HCV + lane];
        acc.x += w * hv.x; acc.y += w * hv.y;
        acc.z += w * hv.z; acc.w += w * hv.w;
        den += w;
    }
    float inv = 1.f / (den + 1e-16f);
    float4 o;
    o.x = fmaxf(acc.x * inv + b1[lane * 4 + 0], 0.f);
    o.y = fmaxf(acc.y * inv + b1[lane * 4 + 1], 0.f);
    o.z = fmaxf(acc.z * inv + b1[lane * 4 + 2], 0.f);
    o.w = fmaxf(acc.w * inv + b1[lane * 4 + 3], 0.f);
    g_h2v[n * HCV + lane] = o;
}

// ---------------- layer-2 projection + attention logits ----------------
// warp per node; W2 [128,7] in smem
__global__ __launch_bounds__(256) void k_proj2(const float* __restrict__ W2,
                                               const float* __restrict__ as2,
                                               const float* __restrict__ ad2) {
    __shared__ float W2s[HC * NCLS];   // 896
    const int tid = threadIdx.x;
#pragma unroll
    for (int i = 0; i < 4; i++) {
        int idx = tid + i * 256;
        if (idx < HC * NCLS) W2s[idx] = W2[idx];
    }
    __syncthreads();

    int warp = (blockIdx.x * blockDim.x + tid) >> 5;
    int lane = tid & 31;
    if (warp >= NND) return;
    const int n = warp;

    float4 v = g_h2v[n * HCV + lane];
    float av[4] = {v.x, v.y, v.z, v.w};
    float acc[NCLS];
#pragma unroll
    for (int c = 0; c < NCLS; c++) acc[c] = 0.f;
#pragma unroll
    for (int j = 0; j < 4; j++) {
        const float* wrow = &W2s[(lane * 4 + j) * NCLS];
#pragma unroll
        for (int c = 0; c < NCLS; c++) acc[c] += av[j] * wrow[c];
    }
#pragma unroll
    for (int c = 0; c < NCLS; c++) {
#pragma unroll
        for (int off = 16; off > 0; off >>= 1)
            acc[c] += __shfl_down_sync(0xFFFFFFFFu, acc[c], off);
    }
    if (lane == 0) {
        float s = 0.f, d = 0.f;
#pragma unroll
        for (int c = 0; c < NCLS; c++) {
            g_p2[n * NCLS + c] = acc[c];
            s += acc[c] * as2[c];
            d += acc[c] * ad2[c];
        }
        g_a2s[n] = s;
        g_a2d[n] = d;
    }
}

// ---------------- layer-2 aggregation -> output ----------------
// 8 lanes per dst node (lane c handles class c, lane 7 helps only with den)
__global__ __launch_bounds__(256) void k_agg2(const float* __restrict__ b2,
                                              float* __restrict__ out) {
    int t = blockIdx.x * blockDim.x + threadIdx.x;
    int n = t >> 3;
    int c = t & 7;
    if (n >= NND) return;

    const float ad = g_a2d[n];
    const int beg = g_offs[n];
    const int deg = g_deg[n];
    float acc = 0.f, den = 0.f;
    for (int i = 0; i < deg; i++) {
        int src = g_csrc[beg + i];
        float e = g_a2s[src] + ad;
        e = (e > 0.f) ? e : NEG * e;
        float w = __expf(e);
        den += w;
        if (c < NCLS) acc += w * g_p2[src * NCLS + c];
    }
    if (c < NCLS) out[n * NCLS + c] = acc / (den + 1e-16f) + b2[c];
}

// ---------------- launch ----------------
extern "C" void kernel_launch(void* const* d_in, const int* in_sizes, int n_in,
                              void* d_out, int out_size) {
    const float* x   = (const float*)d_in[0];
    const void*  ei  = d_in[1];                 // int32 or int64, detected on device
    const float* W1  = (const float*)d_in[2];
    const float* as1 = (const float*)d_in[3];
    const float* ad1 = (const float*)d_in[4];
    const float* b1  = (const float*)d_in[5];
    const float* W2  = (const float*)d_in[6];
    const float* as2 = (const float*)d_in[7];
    const float* ad2 = (const float*)d_in[8];
    const float* b2  = (const float*)d_in[9];
    float* out = (float*)d_out;

    // Detect edge_index dtype, then build CSR (shared by both layers)
    k_detect<<<1, 256>>>((const unsigned int*)ei);
    k_zero_deg<<<(NND + 255) / 256, 256>>>();
    k_hist<<<(NET + 255) / 256, 256>>>(ei);
    k_scan<<<1, 1024>>>();
    k_scatter<<<(NET + 255) / 256, 256>>>(ei);

    // Layer 1
    k_gemm1<<<(NND + BM - 1) / BM, 256>>>(x, W1);
    k_att1<<<(NND * H1 + 255) / 256, 256>>>(as1, ad1);
    k_agg1<<<(NND * 32 + 255) / 256, 256>>>(b1);

    // Layer 2
    k_proj2<<<(NND * 32 + 255) / 256, 256>>>(W2, as2, ad2);
    k_agg2<<<(NND * 8 + 255) / 256, 256>>>(b2, out);
}

// round 9
// speedup vs baseline: 1.5279x; 1.5279x over previous
#include <cuda_runtime.h>
#include <cuda_bf16.h>

// Problem constants (fixed shapes)
#define NND   50000
#define NE    800000
#define NET   850000      // E + N self loops
#define FIN   500
#define H1    8
#define C1    16
#define HC    128         // H1*C1
#define HCV   32          // HC/4 float4s per node
#define NCLS  7
#define NEG   0.2f
#define NBLK  196         // ceil(NND/256) scan blocks

// ---------------- scratch (static device globals; no allocs) ----------------
__device__ float4 g_h1v[NND * HCV];    // layer1 features h = x@W1 (vec4)
__device__ float  g_asrc1[NND * H1];
__device__ float  g_adst1[NND * H1];
__device__ float4 g_h2v[NND * HCV];    // relu(agg1 + b1) (vec4)
__device__ float  g_p2[NND * NCLS];    // layer2 projected
__device__ float  g_a2s[NND];
__device__ float  g_a2d[NND];
__device__ int    g_deg[NND];
__device__ int    g_offs[NND];
__device__ int    g_cur[NND];
__device__ int    g_part[NBLK];        // per-block degree partial sums
__device__ int    g_poff[NBLK];        // scanned partials
__device__ int    g_csrc[NET];         // CSR: sources of incoming edges per dst
__device__ int    g_is64;              // 1 if edge_index is int64, 0 if int32

// ---------------- dtype detection ----------------
// For int64 edge data (values < 2^31), every odd 32-bit word is the zero high
// half. For int32 data, odd words are real node ids (random in [0,50000)).
__global__ __launch_bounds__(256) void k_detect(const unsigned int* __restrict__ w) {
    __shared__ unsigned int s[256];
    unsigned int v = 0;
    for (int i = threadIdx.x; i < 8192; i += 256) v |= w[2 * i + 1];
    s[threadIdx.x] = v;
    __syncthreads();
    for (int off = 128; off > 0; off >>= 1) {
        if (threadIdx.x < off) s[threadIdx.x] |= s[threadIdx.x + off];
        __syncthreads();
    }
    if (threadIdx.x == 0) g_is64 = (s[0] == 0u) ? 1 : 0;
}

__device__ __forceinline__ int load_edge(const void* ei, long long idx) {
    if (g_is64) return (int)((const long long*)ei)[idx];
    return ((const int*)ei)[idx];
}

// ---------------- CSR build ----------------
__global__ __launch_bounds__(256) void k_zero_deg() {
    int i = blockIdx.x * blockDim.x + threadIdx.x;
    if (i < NND) g_deg[i] = 0;
}

__global__ __launch_bounds__(256) void k_hist(const void* __restrict__ ei) {
    int e = blockIdx.x * blockDim.x + threadIdx.x;
    if (e >= NET) return;
    int dst = (e < NE) ? load_edge(ei, (long long)NE + e) : (e - NE);
    if ((unsigned)dst < NND) atomicAdd(&g_deg[dst], 1);
}

// phase A: per-block partial sums of degrees
__global__ __launch_bounds__(256) void k_scanA() {
    __shared__ int s[256];
    int i = blockIdx.x * 256 + threadIdx.x;
    s[threadIdx.x] = (i < NND) ? g_deg[i] : 0;
    __syncthreads();
    for (int off = 128; off > 0; off >>= 1) {
        if (threadIdx.x < off) s[threadIdx.x] += s[threadIdx.x + off];
        __syncthreads();
    }
    if (threadIdx.x == 0) g_part[blockIdx.x] = s[0];
}

// phase B: scan the 196 partials (1 block)
__global__ __launch_bounds__(256) void k_scanB() {
    __shared__ int s[256];
    int t = threadIdx.x;
    int v = (t < NBLK) ? g_part[t] : 0;
    s[t] = v;
    __syncthreads();
    for (int off = 1; off < 256; off <<= 1) {
        int u = 0;
        if (t >= off) u = s[t - off];
        __syncthreads();
        s[t] += u;
        __syncthreads();
    }
    if (t < NBLK) g_poff[t] = s[t] - v;   // exclusive
}

// phase C: per-block exclusive scan + base -> offsets
__global__ __launch_bounds__(256) void k_scanC() {
    __shared__ int s[256];
    int t = threadIdx.x;
    int i = blockIdx.x * 256 + t;
    int v = (i < NND) ? g_deg[i] : 0;
    s[t] = v;
    __syncthreads();
    for (int off = 1; off < 256; off <<= 1) {
        int u = 0;
        if (t >= off) u = s[t - off];
        __syncthreads();
        s[t] += u;
        __syncthreads();
    }
    if (i < NND) {
        int o = g_poff[blockIdx.x] + s[t] - v;
        g_offs[i] = o;
        g_cur[i]  = o;
    }
}

__global__ __launch_bounds__(256) void k_scatter(const void* __restrict__ ei) {
    int e = blockIdx.x * blockDim.x + threadIdx.x;
    if (e >= NET) return;
    int src, dst;
    if (e < NE) {
        src = load_edge(ei, e);
        dst = load_edge(ei, (long long)NE + e);
    } else {
        src = e - NE; dst = e - NE;
    }
    if ((unsigned)dst >= NND || (unsigned)src >= NND) return;  // defensive
    int pos = atomicAdd(&g_cur[dst], 1);
    if ((unsigned)pos < NET) g_csrc[pos] = src;
}

// ---------------- GEMM1: h1 = x @ W1   [50000,500]x[500,128] ----------------
// 256 threads: tx = tid&31 -> 4-col group; ty = tid>>5 -> 16-row group.
// Each thread: 16 rows x 4 cols accumulators; A reads are warp-broadcast
// float4s; B read is one conflict-free float4 per kk.
#define BM 128
#define BK 20
#define APAD 132   // BM+4 pad: breaks store bank conflicts, keeps 16B alignment
__global__ __launch_bounds__(256) void k_gemm1(const float* __restrict__ x,
                                               const float* __restrict__ W1) {
    __shared__ float  As[BK][APAD];     // [k][m]
    __shared__ float4 Bs4[BK][HCV];     // [k][n4]
    const int tid = threadIdx.x;
    const int tx = tid & 31;
    const int ty = tid >> 5;
    const int rowBase = blockIdx.x * BM;

    float acc[16][4];
#pragma unroll
    for (int i = 0; i < 16; i++)
#pragma unroll
        for (int j = 0; j < 4; j++) acc[i][j] = 0.f;

    for (int k0 = 0; k0 < FIN; k0 += BK) {
        // load A tile: 128 rows x 20 k (2560 elems, 10/thread)
#pragma unroll
        for (int i = 0; i < 10; i++) {
            int idx = tid + i * 256;
            int m = idx / BK, k = idx - m * BK;
            int r = rowBase + m;
            float v = 0.f;
            if (r < NND) v = x[(long)r * FIN + k0 + k];
            As[k][m] = v;
        }
        // load B tile: 20 k x 128 n (2560 elems, 10/thread, coalesced)
#pragma unroll
        for (int i = 0; i < 10; i++) {
            int idx = tid + i * 256;
            int k = idx >> 7, nn = idx & 127;
            ((float*)&Bs4[k][0])[nn] = W1[(k0 + k) * HC + nn];
        }
        __syncthreads();
#pragma unroll
        for (int kk = 0; kk < BK; kk++) {
            float4 b4 = Bs4[kk][tx];
            float4 av[4];
#pragma unroll
            for (int q = 0; q < 4; q++)
                av[q] = *(const float4*)&As[kk][ty * 16 + q * 4];
#pragma unroll
            for (int q = 0; q < 4; q++) {
                float am[4] = {av[q].x, av[q].y, av[q].z, av[q].w};
#pragma unroll
                for (int j = 0; j < 4; j++) {
                    float a = am[j];
                    int i = q * 4 + j;
                    acc[i][0] += a * b4.x;
                    acc[i][1] += a * b4.y;
                    acc[i][2] += a * b4.z;
                    acc[i][3] += a * b4.w;
                }
            }
        }
        __syncthreads();
    }
#pragma unroll
    for (int i = 0; i < 16; i++) {
        int r = rowBase + ty * 16 + i;
        if (r < NND) {
            g_h1v[r * HCV + tx] = make_float4(acc[i][0], acc[i][1], acc[i][2], acc[i][3]);
        }
    }
}

// ---------------- per-node attention logits layer 1 ----------------
__global__ __launch_bounds__(256) void k_att1(const float* __restrict__ att_src,
                                              const float* __restrict__ att_dst) {
    int t = blockIdx.x * blockDim.x + threadIdx.x;
    if (t >= NND * H1) return;
    int n = t / H1, h = t - n * H1;
    float ss = 0.f, sd = 0.f;
#pragma unroll
    for (int j = 0; j < 4; j++) {
        float4 v = g_h1v[n * HCV + h * 4 + j];
        ss += v.x * att_src[h * C1 + j * 4 + 0] + v.y * att_src[h * C1 + j * 4 + 1]
            + v.z * att_src[h * C1 + j * 4 + 2] + v.w * att_src[h * C1 + j * 4 + 3];
        sd += v.x * att_dst[h * C1 + j * 4 + 0] + v.y * att_dst[h * C1 + j * 4 + 1]
            + v.z * att_dst[h * C1 + j * 4 + 2] + v.w * att_dst[h * C1 + j * 4 + 3];
    }
    g_asrc1[t] = ss;
    g_adst1[t] = sd;
}

// ---------------- layer-1 aggregation (gather, softmax-normalized) ----------
// warp per dst node; lane covers one float4 (4 channels), head = lane>>2
__global__ __launch_bounds__(256) void k_agg1(const float* __restrict__ b1) {
    int warp = (blockIdx.x * blockDim.x + threadIdx.x) >> 5;
    int lane = threadIdx.x & 31;
    if (warp >= NND) return;
    const int n = warp;
    const int head = lane >> 2;

    const float ad = g_adst1[n * H1 + head];
    const int beg = g_offs[n];
    const int deg = g_deg[n];

    float4 acc = make_float4(0.f, 0.f, 0.f, 0.f);
    float den = 0.f;
    int t = 0;
    for (; t + 2 <= deg; t += 2) {          // unroll x2 for MLP
        int s0 = g_csrc[beg + t];
        int s1 = g_csrc[beg + t + 1];
        float e0 = g_asrc1[s0 * H1 + head] + ad;
        float e1 = g_asrc1[s1 * H1 + head] + ad;
        float4 h0 = g_h1v[s0 * HCV + lane];
        float4 h1 = g_h1v[s1 * HCV + lane];
        e0 = (e0 > 0.f) ? e0 : NEG * e0;
        e1 = (e1 > 0.f) ? e1 : NEG * e1;
        float w0 = __expf(e0);
        float w1 = __expf(e1);
        acc.x += w0 * h0.x + w1 * h1.x;
        acc.y += w0 * h0.y + w1 * h1.y;
        acc.z += w0 * h0.z + w1 * h1.z;
        acc.w += w0 * h0.w + w1 * h1.w;
        den += w0 + w1;
    }
    if (t < deg) {
        int s0 = g_csrc[beg + t];
        float e0 = g_asrc1[s0 * H1 + head] + ad;
        float4 h0 = g_h1v[s0 * HCV + lane];
        e0 = (e0 > 0.f) ? e0 : NEG * e0;
        float w0 = __expf(e0);
        acc.x += w0 * h0.x; acc.y += w0 * h0.y;
        acc.z += w0 * h0.z; acc.w += w0 * h0.w;
        den += w0;
    }
    float inv = 1.f / (den + 1e-16f);
    float4 o;
    o.x = fmaxf(acc.x * inv + b1[lane * 4 + 0], 0.f);
    o.y = fmaxf(acc.y * inv + b1[lane * 4 + 1], 0.f);
    o.z = fmaxf(acc.z * inv + b1[lane * 4 + 2], 0.f);
    o.w = fmaxf(acc.w * inv + b1[lane * 4 + 3], 0.f);
    g_h2v[n * HCV + lane] = o;
}

// ---------------- layer-2 projection + attention logits ----------------
// warp per node; W2 [128,7] in smem
__global__ __launch_bounds__(256) void k_proj2(const float* __restrict__ W2,
                                               const float* __restrict__ as2,
                                               const float* __restrict__ ad2) {
    __shared__ float W2s[HC * NCLS];   // 896
    const int tid = threadIdx.x;
#pragma unroll
    for (int i = 0; i < 4; i++) {
        int idx = tid + i * 256;
        if (idx < HC * NCLS) W2s[idx] = W2[idx];
    }
    __syncthreads();

    int warp = (blockIdx.x * blockDim.x + tid) >> 5;
    int lane = tid & 31;
    if (warp >= NND) return;
    const int n = warp;

    float4 v = g_h2v[n * HCV + lane];
    float av[4] = {v.x, v.y, v.z, v.w};
    float acc[NCLS];
#pragma unroll
    for (int c = 0; c < NCLS; c++) acc[c] = 0.f;
#pragma unroll
    for (int j = 0; j < 4; j++) {
        const float* wrow = &W2s[(lane * 4 + j) * NCLS];
#pragma unroll
        for (int c = 0; c < NCLS; c++) acc[c] += av[j] * wrow[c];
    }
#pragma unroll
    for (int c = 0; c < NCLS; c++) {
#pragma unroll
        for (int off = 16; off > 0; off >>= 1)
            acc[c] += __shfl_down_sync(0xFFFFFFFFu, acc[c], off);
    }
    if (lane == 0) {
        float s = 0.f, d = 0.f;
#pragma unroll
        for (int c = 0; c < NCLS; c++) {
            g_p2[n * NCLS + c] = acc[c];
            s += acc[c] * as2[c];
            d += acc[c] * ad2[c];
        }
        g_a2s[n] = s;
        g_a2d[n] = d;
    }
}

// ---------------- layer-2 aggregation -> output ----------------
// 8 lanes per dst node (lane c handles class c, lane 7 helps only with den)
__global__ __launch_bounds__(256) void k_agg2(const float* __restrict__ b2,
                                              float* __restrict__ out) {
    int t = blockIdx.x * blockDim.x + threadIdx.x;
    int n = t >> 3;
    int c = t & 7;
    if (n >= NND) return;

    const float ad = g_a2d[n];
    const int beg = g_offs[n];
    const int deg = g_deg[n];
    float acc = 0.f, den = 0.f;
    int i = 0;
    for (; i + 2 <= deg; i += 2) {
        int s0 = g_csrc[beg + i];
        int s1 = g_csrc[beg + i + 1];
        float e0 = g_a2s[s0] + ad;
        float e1 = g_a2s[s1] + ad;
        float p0 = (c < NCLS) ? g_p2[s0 * NCLS + c] : 0.f;
        float p1 = (c < NCLS) ? g_p2[s1 * NCLS + c] : 0.f;
        e0 = (e0 > 0.f) ? e0 : NEG * e0;
        e1 = (e1 > 0.f) ? e1 : NEG * e1;
        float w0 = __expf(e0);
        float w1 = __expf(e1);
        den += w0 + w1;
        acc += w0 * p0 + w1 * p1;
    }
    if (i < deg) {
        int s0 = g_csrc[beg + i];
        float e0 = g_a2s[s0] + ad;
        float p0 = (c < NCLS) ? g_p2[s0 * NCLS + c] : 0.f;
        e0 = (e0 > 0.f) ? e0 : NEG * e0;
        float w0 = __expf(e0);
        den += w0;
        acc += w0 * p0;
    }
    if (c < NCLS) out[n * NCLS + c] = acc / (den + 1e-16f) + b2[c];
}

// ---------------- launch ----------------
extern "C" void kernel_launch(void* const* d_in, const int* in_sizes, int n_in,
                              void* d_out, int out_size) {
    const float* x   = (const float*)d_in[0];
    const void*  ei  = d_in[1];                 // int32 or int64, detected on device
    const float* W1  = (const float*)d_in[2];
    const float* as1 = (const float*)d_in[3];
    const float* ad1 = (const float*)d_in[4];
    const float* b1  = (const float*)d_in[5];
    const float* W2  = (const float*)d_in[6];
    const float* as2 = (const float*)d_in[7];
    const float* ad2 = (const float*)d_in[8];
    const float* b2  = (const float*)d_in[9];
    float* out = (float*)d_out;

    // CSR build (shared by both layers); gemm1 placed as 6th launch so the
    // ncu -s 5 -c 1 capture profiles it.
    k_detect<<<1, 256>>>((const unsigned int*)ei);          // 1
    k_zero_deg<<<(NND + 255) / 256, 256>>>();               // 2
    k_hist<<<(NET + 255) / 256, 256>>>(ei);                 // 3
    k_scanA<<<NBLK, 256>>>();                               // 4
    k_scanB<<<1, 256>>>();                                  // 5
    k_gemm1<<<(NND + BM - 1) / BM, 256>>>(x, W1);           // 6  (profiled)
    k_scanC<<<NBLK, 256>>>();                               // 7
    k_scatter<<<(NET + 255) / 256, 256>>>(ei);              // 8

    // Layer 1
    k_att1<<<(NND * H1 + 255) / 256, 256>>>(as1, ad1);      // 9
    k_agg1<<<(NND * 32 + 255) / 256, 256>>>(b1);            // 10

    // Layer 2
    k_proj2<<<(NND * 32 + 255) / 256, 256>>>(W2, as2, ad2); // 11
    k_agg2<<<(NND * 8 + 255) / 256, 256>>>(b2, out);        // 12
}

// round 11
// speedup vs baseline: 2.1309x; 1.3947x over previous
#include <cuda_runtime.h>
#include <cuda_bf16.h>

// Problem constants (fixed shapes)
#define NND   50000
#define NE    800000
#define NET   850000      // E + N self loops
#define FIN   500
#define KPAD  512         // FIN padded for MMA k-tiling
#define H1    8
#define C1    16
#define HC    128         // H1*C1
#define HCV   32          // HC/4 float4s per node
#define NCLS  7
#define NEG   0.2f
#define NBLK  196         // ceil(NND/256) scan blocks

// ---------------- scratch (static device globals; no allocs) ----------------
__device__ float4 g_h1v[NND * HCV];    // layer1 features h = x@W1 (vec4)
__device__ float  g_asrc1[NND * H1];
__device__ float  g_adst1[NND * H1];
__device__ float4 g_h2v[NND * HCV];    // relu(agg1 + b1) (vec4)
__device__ float  g_p2[NND * NCLS];    // layer2 projected
__device__ float  g_a2s[NND];
__device__ float  g_a2d[NND];
__device__ int    g_deg[NND];
__device__ int    g_offs[NND];
__device__ int    g_cur[NND];
__device__ int    g_part[NBLK];        // per-block degree partial sums
__device__ int    g_poff[NBLK];        // scanned partials
__device__ int    g_csrc[NET];         // CSR: sources of incoming edges per dst
__device__ int    g_is64;              // 1 if edge_index is int64, 0 if int32
__device__ __nv_bfloat16 g_w1h[HC * KPAD];  // W1^T bf16 hi  [n][k]
__device__ __nv_bfloat16 g_w1l[HC * KPAD];  // W1^T bf16 lo  [n][k]

// ---------------- dtype detection ----------------
__global__ __launch_bounds__(256) void k_detect(const unsigned int* __restrict__ w) {
    __shared__ unsigned int s[256];
    unsigned int v = 0;
    for (int i = threadIdx.x; i < 8192; i += 256) v |= w[2 * i + 1];
    s[threadIdx.x] = v;
    __syncthreads();
    for (int off = 128; off > 0; off >>= 1) {
        if (threadIdx.x < off) s[threadIdx.x] |= s[threadIdx.x + off];
        __syncthreads();
    }
    if (threadIdx.x == 0) g_is64 = (s[0] == 0u) ? 1 : 0;
}

__device__ __forceinline__ int load_edge(const void* ei, long long idx) {
    if (g_is64) return (int)((const long long*)ei)[idx];
    return ((const int*)ei)[idx];
}

// ---------------- CSR build ----------------
__global__ __launch_bounds__(256) void k_zero_deg() {
    int i = blockIdx.x * blockDim.x + threadIdx.x;
    if (i < NND) g_deg[i] = 0;
}

__global__ __launch_bounds__(256) void k_hist(const void* __restrict__ ei) {
    int e = blockIdx.x * blockDim.x + threadIdx.x;
    if (e >= NET) return;
    int dst = (e < NE) ? load_edge(ei, (long long)NE + e) : (e - NE);
    if ((unsigned)dst < NND) atomicAdd(&g_deg[dst], 1);
}

__global__ __launch_bounds__(256) void k_scanA() {
    __shared__ int s[256];
    int i = blockIdx.x * 256 + threadIdx.x;
    s[threadIdx.x] = (i < NND) ? g_deg[i] : 0;
    __syncthreads();
    for (int off = 128; off > 0; off >>= 1) {
        if (threadIdx.x < off) s[threadIdx.x] += s[threadIdx.x + off];
        __syncthreads();
    }
    if (threadIdx.x == 0) g_part[blockIdx.x] = s[0];
}

__global__ __launch_bounds__(256) void k_scanB() {
    __shared__ int s[256];
    int t = threadIdx.x;
    int v = (t < NBLK) ? g_part[t] : 0;
    s[t] = v;
    __syncthreads();
    for (int off = 1; off < 256; off <<= 1) {
        int u = 0;
        if (t >= off) u = s[t - off];
        __syncthreads();
        s[t] += u;
        __syncthreads();
    }
    if (t < NBLK) g_poff[t] = s[t] - v;   // exclusive
}

__global__ __launch_bounds__(256) void k_scanC() {
    __shared__ int s[256];
    int t = threadIdx.x;
    int i = blockIdx.x * 256 + t;
    int v = (i < NND) ? g_deg[i] : 0;
    s[t] = v;
    __syncthreads();
    for (int off = 1; off < 256; off <<= 1) {
        int u = 0;
        if (t >= off) u = s[t - off];
        __syncthreads();
        s[t] += u;
        __syncthreads();
    }
    if (i < NND) {
        int o = g_poff[blockIdx.x] + s[t] - v;
        g_offs[i] = o;
        g_cur[i]  = o;
    }
}

__global__ __launch_bounds__(256) void k_scatter(const void* __restrict__ ei) {
    int e = blockIdx.x * blockDim.x + threadIdx.x;
    if (e >= NET) return;
    int src, dst;
    if (e < NE) {
        src = load_edge(ei, e);
        dst = load_edge(ei, (long long)NE + e);
    } else {
        src = e - NE; dst = e - NE;
    }
    if ((unsigned)dst >= NND || (unsigned)src >= NND) return;
    int pos = atomicAdd(&g_cur[dst], 1);
    if ((unsigned)pos < NET) g_csrc[pos] = src;
}

// ---------------- W1 prep: transpose + bf16 hi/lo split ----------------
__global__ __launch_bounds__(256) void k_prepw(const float* __restrict__ W1) {
    int idx = blockIdx.x * 256 + threadIdx.x;     // 128*512 = 65536
    if (idx >= HC * KPAD) return;
    int n = idx >> 9, k = idx & (KPAD - 1);
    float v = (k < FIN) ? W1[k * HC + n] : 0.f;
    __nv_bfloat16 h = __float2bfloat16(v);
    float lo = v - __bfloat162float(h);
    g_w1h[idx] = h;
    g_w1l[idx] = __float2bfloat16(lo);
}

// ---------------- GEMM1 (tensor cores): h1 = x @ W1 -----------------------
// C tile 128x128 per CTA, 8 warps: wm = wid&3 (32 rows), wn = wid>>2 (64 cols).
// bf16 3-term split: xh*wh + xh*wl + xl*wh, fp32 accumulate.
#define AP 40   // smem row pad (bf16 units): 80B rows -> conflict-free frags
__device__ __forceinline__ void mma16816(float* d, const unsigned* a,
                                         unsigned b0, unsigned b1) {
    asm volatile(
        "mma.sync.aligned.m16n8k16.row.col.f32.bf16.bf16.f32 "
        "{%0,%1,%2,%3}, {%4,%5,%6,%7}, {%8,%9}, {%0,%1,%2,%3};"
        : "+f"(d[0]), "+f"(d[1]), "+f"(d[2]), "+f"(d[3])
        : "r"(a[0]), "r"(a[1]), "r"(a[2]), "r"(a[3]), "r"(b0), "r"(b1));
}

__global__ __launch_bounds__(256, 2) void k_gemm1(const float* __restrict__ x) {
    __shared__ __nv_bfloat16 Ash[128][AP];
    __shared__ __nv_bfloat16 Asl[128][AP];
    __shared__ __nv_bfloat16 Bsh[128][AP];
    __shared__ __nv_bfloat16 Bsl[128][AP];

    const int tid  = threadIdx.x;
    const int lane = tid & 31;
    const int wid  = tid >> 5;
    const int wm   = wid & 3;        // m-warp: rows wm*32
    const int wn   = wid >> 2;       // n-warp: cols wn*64
    const int gr   = lane >> 2;      // 0..7
    const int q2   = (lane & 3) * 2; // 0,2,4,6
    const int rowBase = blockIdx.x * 128;

    float d[2][8][4];
#pragma unroll
    for (int a = 0; a < 2; a++)
#pragma unroll
        for (int b = 0; b < 8; b++)
#pragma unroll
            for (int c = 0; c < 4; c++) d[a][b][c] = 0.f;

    const int arow = tid >> 1;             // 0..127
    const int akb  = (tid & 1) * 16;       // 0 or 16

    for (int k0 = 0; k0 < KPAD; k0 += 32) {
        // ---- load + split A tile: x[rowBase..+128][k0..k0+32] ----
        {
            int r = rowBase + arow;
            const float* xp = x + (long)r * FIN + k0 + akb;
#pragma unroll
            for (int q = 0; q < 4; q++) {
                int kk = akb + q * 4;
                float4 v = make_float4(0.f, 0.f, 0.f, 0.f);
                if (r < NND && (k0 + kk) < FIN) v = *(const float4*)(xp + q * 4);
                __nv_bfloat16 h0 = __float2bfloat16(v.x);
                __nv_bfloat16 h1 = __float2bfloat16(v.y);
                __nv_bfloat16 h2 = __float2bfloat16(v.z);
                __nv_bfloat16 h3 = __float2bfloat16(v.w);
                __nv_bfloat16 l0 = __float2bfloat16(v.x - __bfloat162float(h0));
                __nv_bfloat16 l1 = __float2bfloat16(v.y - __bfloat162float(h1));
                __nv_bfloat16 l2 = __float2bfloat16(v.z - __bfloat162float(h2));
                __nv_bfloat16 l3 = __float2bfloat16(v.w - __bfloat162float(h3));
                *(__nv_bfloat162*)&Ash[arow][kk]     = __halves2bfloat162(h0, h1);
                *(__nv_bfloat162*)&Ash[arow][kk + 2] = __halves2bfloat162(h2, h3);
                *(__nv_bfloat162*)&Asl[arow][kk]     = __halves2bfloat162(l0, l1);
                *(__nv_bfloat162*)&Asl[arow][kk + 2] = __halves2bfloat162(l2, l3);
            }
        }
        // ---- load B tiles (pre-split, n-major) ----
        {
            int n  = tid >> 1;
            int kb = (tid & 1) * 16;
            const uint4* bh = (const uint4*)&g_w1h[n * KPAD + k0 + kb];
            const uint4* bl = (const uint4*)&g_w1l[n * KPAD + k0 + kb];
            uint4 u0 = bh[0], u1 = bh[1];
            uint4 v0 = bl[0], v1 = bl[1];
            unsigned* dsth = (unsigned*)&Bsh[n][kb];
            unsigned* dstl = (unsigned*)&Bsl[n][kb];
            dsth[0] = u0.x; dsth[1] = u0.y; dsth[2] = u0.z; dsth[3] = u0.w;
            dsth[4] = u1.x; dsth[5] = u1.y; dsth[6] = u1.z; dsth[7] = u1.w;
            dstl[0] = v0.x; dstl[1] = v0.y; dstl[2] = v0.z; dstl[3] = v0.w;
            dstl[4] = v1.x; dstl[5] = v1.y; dstl[6] = v1.z; dstl[7] = v1.w;
        }
        __syncthreads();
        // ---- MMA over the 32-k tile (two k16 steps) ----
#pragma unroll
        for (int kk = 0; kk < 32; kk += 16) {
            unsigned ah[2][4], al[2][4];
#pragma unroll
            for (int mt = 0; mt < 2; mt++) {
                int rb = wm * 32 + mt * 16;
                ah[mt][0] = *(const unsigned*)&Ash[rb + gr][kk + q2];
                ah[mt][1] = *(const unsigned*)&Ash[rb + gr + 8][kk + q2];
                ah[mt][2] = *(const unsigned*)&Ash[rb + gr][kk + q2 + 8];
                ah[mt][3] = *(const unsigned*)&Ash[rb + gr + 8][kk + q2 + 8];
                al[mt][0] = *(const unsigned*)&Asl[rb + gr][kk + q2];
                al[mt][1] = *(const unsigned*)&Asl[rb + gr + 8][kk + q2];
                al[mt][2] = *(const unsigned*)&Asl[rb + gr][kk + q2 + 8];
                al[mt][3] = *(const unsigned*)&Asl[rb + gr + 8][kk + q2 + 8];
            }
#pragma unroll
            for (int nt = 0; nt < 8; nt++) {
                int nb = wn * 64 + nt * 8 + gr;
                unsigned bh0 = *(const unsigned*)&Bsh[nb][kk + q2];
                unsigned bh1 = *(const unsigned*)&Bsh[nb][kk + q2 + 8];
                unsigned bl0 = *(const unsigned*)&Bsl[nb][kk + q2];
                unsigned bl1 = *(const unsigned*)&Bsl[nb][kk + q2 + 8];
#pragma unroll
                for (int mt = 0; mt < 2; mt++) {
                    mma16816(d[mt][nt], ah[mt], bh0, bh1);
                    mma16816(d[mt][nt], ah[mt], bl0, bl1);
                    mma16816(d[mt][nt], al[mt], bh0, bh1);
                }
            }
        }
        __syncthreads();
    }
    // ---- store ----
    float* out = (float*)g_h1v;
#pragma unroll
    for (int mt = 0; mt < 2; mt++) {
#pragma unroll
        for (int nt = 0; nt < 8; nt++) {
            int r0 = rowBase + wm * 32 + mt * 16 + gr;
            int c  = wn * 64 + nt * 8 + q2;
            if (r0 < NND) {
                float2 v0 = make_float2(d[mt][nt][0], d[mt][nt][1]);
                *(float2*)&out[(long)r0 * HC + c] = v0;
            }
            int r1 = r0 + 8;
            if (r1 < NND) {
                float2 v1 = make_float2(d[mt][nt][2], d[mt][nt][3]);
                *(float2*)&out[(long)r1 * HC + c] = v1;
            }
        }
    }
}

// ---------------- per-node attention logits layer 1 ----------------
__global__ __launch_bounds__(256) void k_att1(const float* __restrict__ att_src,
                                              const float* __restrict__ att_dst) {
    int t = blockIdx.x * blockDim.x + threadIdx.x;
    if (t >= NND * H1) return;
    int n = t / H1, h = t - n * H1;
    float ss = 0.f, sd = 0.f;
#pragma unroll
    for (int j = 0; j < 4; j++) {
        float4 v = g_h1v[n * HCV + h * 4 + j];
        ss += v.x * att_src[h * C1 + j * 4 + 0] + v.y * att_src[h * C1 + j * 4 + 1]
            + v.z * att_src[h * C1 + j * 4 + 2] + v.w * att_src[h * C1 + j * 4 + 3];
        sd += v.x * att_dst[h * C1 + j * 4 + 0] + v.y * att_dst[h * C1 + j * 4 + 1]
            + v.z * att_dst[h * C1 + j * 4 + 2] + v.w * att_dst[h * C1 + j * 4 + 3];
    }
    g_asrc1[t] = ss;
    g_adst1[t] = sd;
}

// ---------------- layer-1 aggregation ----------
__global__ __launch_bounds__(256) void k_agg1(const float* __restrict__ b1) {
    int warp = (blockIdx.x * blockDim.x + threadIdx.x) >> 5;
    int lane = threadIdx.x & 31;
    if (warp >= NND) return;
    const int n = warp;
    const int head = lane >> 2;

    const float ad = g_adst1[n * H1 + head];
    const int beg = g_offs[n];
    const int deg = g_deg[n];

    float4 acc = make_float4(0.f, 0.f, 0.f, 0.f);
    float den = 0.f;
    int t = 0;
    for (; t + 2 <= deg; t += 2) {
        int s0 = g_csrc[beg + t];
        int s1 = g_csrc[beg + t + 1];
        float e0 = g_asrc1[s0 * H1 + head] + ad;
        float e1 = g_asrc1[s1 * H1 + head] + ad;
        float4 h0 = g_h1v[s0 * HCV + lane];
        float4 h1 = g_h1v[s1 * HCV + lane];
        e0 = (e0 > 0.f) ? e0 : NEG * e0;
        e1 = (e1 > 0.f) ? e1 : NEG * e1;
        float w0 = __expf(e0);
        float w1 = __expf(e1);
        acc.x += w0 * h0.x + w1 * h1.x;
        acc.y += w0 * h0.y + w1 * h1.y;
        acc.z += w0 * h0.z + w1 * h1.z;
        acc.w += w0 * h0.w + w1 * h1.w;
        den += w0 + w1;
    }
    if (t < deg) {
        int s0 = g_csrc[beg + t];
        float e0 = g_asrc1[s0 * H1 + head] + ad;
        float4 h0 = g_h1v[s0 * HCV + lane];
        e0 = (e0 > 0.f) ? e0 : NEG * e0;
        float w0 = __expf(e0);
        acc.x += w0 * h0.x; acc.y += w0 * h0.y;
        acc.z += w0 * h0.z; acc.w += w0 * h0.w;
        den += w0;
    }
    float inv = 1.f / (den + 1e-16f);
    float4 o;
    o.x = fmaxf(acc.x * inv + b1[lane * 4 + 0], 0.f);
    o.y = fmaxf(acc.y * inv + b1[lane * 4 + 1], 0.f);
    o.z = fmaxf(acc.z * inv + b1[lane * 4 + 2], 0.f);
    o.w = fmaxf(acc.w * inv + b1[lane * 4 + 3], 0.f);
    g_h2v[n * HCV + lane] = o;
}

// ---------------- layer-2 projection + attention logits ----------------
__global__ __launch_bounds__(256) void k_proj2(const float* __restrict__ W2,
                                               const float* __restrict__ as2,
                                               const float* __restrict__ ad2) {
    __shared__ float W2s[HC * NCLS];
    const int tid = threadIdx.x;
#pragma unroll
    for (int i = 0; i < 4; i++) {
        int idx = tid + i * 256;
        if (idx < HC * NCLS) W2s[idx] = W2[idx];
    }
    __syncthreads();

    int warp = (blockIdx.x * blockDim.x + tid) >> 5;
    int lane = tid & 31;
    if (warp >= NND) return;
    const int n = warp;

    float4 v = g_h2v[n * HCV + lane];
    float av[4] = {v.x, v.y, v.z, v.w};
    float acc[NCLS];
#pragma unroll
    for (int c = 0; c < NCLS; c++) acc[c] = 0.f;
#pragma unroll
    for (int j = 0; j < 4; j++) {
        const float* wrow = &W2s[(lane * 4 + j) * NCLS];
#pragma unroll
        for (int c = 0; c < NCLS; c++) acc[c] += av[j] * wrow[c];
    }
#pragma unroll
    for (int c = 0; c < NCLS; c++) {
#pragma unroll
        for (int off = 16; off > 0; off >>= 1)
            acc[c] += __shfl_down_sync(0xFFFFFFFFu, acc[c], off);
    }
    if (lane == 0) {
        float s = 0.f, d2 = 0.f;
#pragma unroll
        for (int c = 0; c < NCLS; c++) {
            g_p2[n * NCLS + c] = acc[c];
            s  += acc[c] * as2[c];
            d2 += acc[c] * ad2[c];
        }
        g_a2s[n] = s;
        g_a2d[n] = d2;
    }
}

// ---------------- layer-2 aggregation -> output ----------------
__global__ __launch_bounds__(256) void k_agg2(const float* __restrict__ b2,
                                              float* __restrict__ out) {
    int t = blockIdx.x * blockDim.x + threadIdx.x;
    int n = t >> 3;
    int c = t & 7;
    if (n >= NND) return;

    const float ad = g_a2d[n];
    const int beg = g_offs[n];
    const int deg = g_deg[n];
    float acc = 0.f, den = 0.f;
    int i = 0;
    for (; i + 2 <= deg; i += 2) {
        int s0 = g_csrc[beg + i];
        int s1 = g_csrc[beg + i + 1];
        float e0 = g_a2s[s0] + ad;
        float e1 = g_a2s[s1] + ad;
        float p0 = (c < NCLS) ? g_p2[s0 * NCLS + c] : 0.f;
        float p1 = (c < NCLS) ? g_p2[s1 * NCLS + c] : 0.f;
        e0 = (e0 > 0.f) ? e0 : NEG * e0;
        e1 = (e1 > 0.f) ? e1 : NEG * e1;
        float w0 = __expf(e0);
        float w1 = __expf(e1);
        den += w0 + w1;
        acc += w0 * p0 + w1 * p1;
    }
    if (i < deg) {
        int s0 = g_csrc[beg + i];
        float e0 = g_a2s[s0] + ad;
        float p0 = (c < NCLS) ? g_p2[s0 * NCLS + c] : 0.f;
        e0 = (e0 > 0.f) ? e0 : NEG * e0;
        float w0 = __expf(e0);
        den += w0;
        acc += w0 * p0;
    }
    if (c < NCLS) out[n * NCLS + c] = acc / (den + 1e-16f) + b2[c];
}

// ---------------- launch ----------------
extern "C" void kernel_launch(void* const* d_in, const int* in_sizes, int n_in,
                              void* d_out, int out_size) {
    const float* x   = (const float*)d_in[0];
    const void*  ei  = d_in[1];
    const float* W1  = (const float*)d_in[2];
    const float* as1 = (const float*)d_in[3];
    const float* ad1 = (const float*)d_in[4];
    const float* b1  = (const float*)d_in[5];
    const float* W2  = (const float*)d_in[6];
    const float* as2 = (const float*)d_in[7];
    const float* ad2 = (const float*)d_in[8];
    const float* b2  = (const float*)d_in[9];
    float* out = (float*)d_out;

    k_detect<<<1, 256>>>((const unsigned int*)ei);          // 1
    k_prepw<<<(HC * KPAD + 255) / 256, 256>>>(W1);          // 2
    k_zero_deg<<<(NND + 255) / 256, 256>>>();               // 3
    k_hist<<<(NET + 255) / 256, 256>>>(ei);                 // 4
    k_scanA<<<NBLK, 256>>>();                               // 5
    k_gemm1<<<(NND + 127) / 128, 256>>>(x);                 // 6  (profiled)
    k_scanB<<<1, 256>>>();                                  // 7
    k_scanC<<<NBLK, 256>>>();                               // 8
    k_scatter<<<(NET + 255) / 256, 256>>>(ei);              // 9

    // Layer 1
    k_att1<<<(NND * H1 + 255) / 256, 256>>>(as1, ad1);      // 10
    k_agg1<<<(NND * 32 + 255) / 256, 256>>>(b1);            // 11

    // Layer 2
    k_proj2<<<(NND * 32 + 255) / 256, 256>>>(W2, as2, ad2); // 12
    k_agg2<<<(NND * 8 + 255) / 256, 256>>>(b2, out);        // 13
}

// round 15
// speedup vs baseline: 2.2381x; 1.0503x over previous
#include <cuda_runtime.h>
#include <cuda_bf16.h>

// Problem constants (fixed shapes)
#define NND   50000
#define NE    800000
#define NET   850000      // E + N self loops
#define FIN   500
#define KPAD  512         // FIN padded for MMA k-tiling
#define H1    8
#define C1    16
#define HC    128         // H1*C1
#define HCV   32          // HC/4 float4s per node
#define NCLS  7
#define NEG   0.2f
#define NBLK  196         // ceil(NND/256) scan blocks
#define PREPB 256         // prepw blocks (65536/256)

// ---------------- scratch (static device globals; no allocs) ----------------
__device__ float4 g_h1v[NND * HCV];    // layer1 features h = x@W1 (vec4)
__device__ float  g_asrc1[NND * H1];
__device__ float  g_adst1[NND * H1];
__device__ float  g_p2[NND * NCLS];    // layer2 projected
__device__ float  g_a2s[NND];
__device__ float  g_a2d[NND];
__device__ int    g_deg[NND];
__device__ int    g_offs[NND];
__device__ int    g_cur[NND];
__device__ int    g_part[NBLK];        // per-block degree partial sums
__device__ int    g_poff[NBLK];        // scanned partials
__device__ int    g_csrc[NET];         // CSR: sources of incoming edges per dst
__device__ int    g_is64;              // 1 if edge_index is int64, 0 if int32
__device__ __nv_bfloat16 g_w1h[HC * KPAD];  // W1^T bf16 hi  [n][k]
__device__ __nv_bfloat16 g_w1l[HC * KPAD];  // W1^T bf16 lo  [n][k]

__device__ __forceinline__ int load_edge(const void* ei, long long idx) {
    if (g_is64) return (int)((const long long*)ei)[idx];
    return ((const int*)ei)[idx];
}

// ---------------- setup: dtype detect + zero degrees + W1 split ------------
// blocks: [0] detect, [1..1+NBLK) zero_deg, [1+NBLK..1+NBLK+PREPB) prepw
__global__ __launch_bounds__(256) void k_setup(const unsigned int* __restrict__ w,
                                               const float* __restrict__ W1) {
    int b = blockIdx.x;
    if (b == 0) {
        __shared__ unsigned int s[256];
        unsigned int v = 0;
        for (int i = threadIdx.x; i < 8192; i += 256) v |= w[2 * i + 1];
        s[threadIdx.x] = v;
        __syncthreads();
        for (int off = 128; off > 0; off >>= 1) {
            if (threadIdx.x < off) s[threadIdx.x] |= s[threadIdx.x + off];
            __syncthreads();
        }
        if (threadIdx.x == 0) g_is64 = (s[0] == 0u) ? 1 : 0;
    } else if (b < 1 + NBLK) {
        int i = (b - 1) * 256 + threadIdx.x;
        if (i < NND) g_deg[i] = 0;
    } else {
        int idx = (b - 1 - NBLK) * 256 + threadIdx.x;   // 0..65535
        if (idx < HC * KPAD) {
            int n = idx >> 9, k = idx & (KPAD - 1);
            float v = (k < FIN) ? W1[k * HC + n] : 0.f;
            __nv_bfloat16 h = __float2bfloat16(v);
            float lo = v - __bfloat162float(h);
            g_w1h[idx] = h;
            g_w1l[idx] = __float2bfloat16(lo);
        }
    }
}

// ---------------- CSR build ----------------
__global__ __launch_bounds__(256) void k_hist(const void* __restrict__ ei) {
    int e = blockIdx.x * blockDim.x + threadIdx.x;
    if (e >= NET) return;
    int dst = (e < NE) ? load_edge(ei, (long long)NE + e) : (e - NE);
    if ((unsigned)dst < NND) atomicAdd(&g_deg[dst], 1);
}

__global__ __launch_bounds__(256) void k_scanA() {
    __shared__ int s[256];
    int i = blockIdx.x * 256 + threadIdx.x;
    s[threadIdx.x] = (i < NND) ? g_deg[i] : 0;
    __syncthreads();
    for (int off = 128; off > 0; off >>= 1) {
        if (threadIdx.x < off) s[threadIdx.x] += s[threadIdx.x + off];
        __syncthreads();
    }
    if (threadIdx.x == 0) g_part[blockIdx.x] = s[0];
}

__global__ __launch_bounds__(256) void k_scanB() {
    __shared__ int s[256];
    int t = threadIdx.x;
    int v = (t < NBLK) ? g_part[t] : 0;
    s[t] = v;
    __syncthreads();
    for (int off = 1; off < 256; off <<= 1) {
        int u = 0;
        if (t >= off) u = s[t - off];
        __syncthreads();
        s[t] += u;
        __syncthreads();
    }
    if (t < NBLK) g_poff[t] = s[t] - v;   // exclusive
}

__global__ __launch_bounds__(256) void k_scanC() {
    __shared__ int s[256];
    int t = threadIdx.x;
    int i = blockIdx.x * 256 + t;
    int v = (i < NND) ? g_deg[i] : 0;
    s[t] = v;
    __syncthreads();
    for (int off = 1; off < 256; off <<= 1) {
        int u = 0;
        if (t >= off) u = s[t - off];
        __syncthreads();
        s[t] += u;
        __syncthreads();
    }
    if (i < NND) {
        int o = g_poff[blockIdx.x] + s[t] - v;
        g_offs[i] = o;
        g_cur[i]  = o;
    }
}

__global__ __launch_bounds__(256) void k_scatter(const void* __restrict__ ei) {
    int e = blockIdx.x * blockDim.x + threadIdx.x;
    if (e >= NET) return;
    int src, dst;
    if (e < NE) {
        src = load_edge(ei, e);
        dst = load_edge(ei, (long long)NE + e);
    } else {
        src = e - NE; dst = e - NE;
    }
    if ((unsigned)dst >= NND || (unsigned)src >= NND) return;
    int pos = atomicAdd(&g_cur[dst], 1);
    if ((unsigned)pos < NET) g_csrc[pos] = src;
}

// ---------------- GEMM1 (tensor cores) + fused att1 -----------------------
// C tile 128x128 per CTA, 8 warps: wm = wid&3 (32 rows), wn = wid>>2 (64 cols).
// bf16 3-term split: xh*wh + xh*wl + xl*wh, fp32 accumulate.
// Epilogue computes per-(node,head) attention dots from register tile.
#define AP 40   // smem row pad (bf16 units): 80B rows -> conflict-free frags
__device__ __forceinline__ void mma16816(float* d, const unsigned* a,
                                         unsigned b0, unsigned b1) {
    asm volatile(
        "mma.sync.aligned.m16n8k16.row.col.f32.bf16.bf16.f32 "
        "{%0,%1,%2,%3}, {%4,%5,%6,%7}, {%8,%9}, {%0,%1,%2,%3};"
        : "+f"(d[0]), "+f"(d[1]), "+f"(d[2]), "+f"(d[3])
        : "r"(a[0]), "r"(a[1]), "r"(a[2]), "r"(a[3]), "r"(b0), "r"(b1));
}

__global__ __launch_bounds__(256, 2) void k_gemm1(const float* __restrict__ x,
                                                  const float* __restrict__ as1,
                                                  const float* __restrict__ ad1) {
    __shared__ __nv_bfloat16 Ash[128][AP];
    __shared__ __nv_bfloat16 Asl[128][AP];
    __shared__ __nv_bfloat16 Bsh[128][AP];
    __shared__ __nv_bfloat16 Bsl[128][AP];
    __shared__ float att_s[HC], att_d[HC];

    const int tid  = threadIdx.x;
    const int lane = tid & 31;
    const int wid  = tid >> 5;
    const int wm   = wid & 3;        // m-warp: rows wm*32
    const int wn   = wid >> 2;       // n-warp: cols wn*64
    const int gr   = lane >> 2;      // 0..7
    const int q2   = (lane & 3) * 2; // 0,2,4,6
    const int rowBase = blockIdx.x * 128;

    if (tid < HC) { att_s[tid] = as1[tid]; att_d[tid] = ad1[tid]; }

    float d[2][8][4];
#pragma unroll
    for (int a = 0; a < 2; a++)
#pragma unroll
        for (int b = 0; b < 8; b++)
#pragma unroll
            for (int c = 0; c < 4; c++) d[a][b][c] = 0.f;

    const int arow = tid >> 1;             // 0..127
    const int akb  = (tid & 1) * 16;       // 0 or 16

    for (int k0 = 0; k0 < KPAD; k0 += 32) {
        // ---- load + split A tile: x[rowBase..+128][k0..k0+32] ----
        {
            int r = rowBase + arow;
            const float* xp = x + (long)r * FIN + k0 + akb;
#pragma unroll
            for (int q = 0; q < 4; q++) {
                int kk = akb + q * 4;
                float4 v = make_float4(0.f, 0.f, 0.f, 0.f);
                if (r < NND && (k0 + kk) < FIN) v = *(const float4*)(xp + q * 4);
                __nv_bfloat16 h0 = __float2bfloat16(v.x);
                __nv_bfloat16 h1 = __float2bfloat16(v.y);
                __nv_bfloat16 h2 = __float2bfloat16(v.z);
                __nv_bfloat16 h3 = __float2bfloat16(v.w);
                __nv_bfloat16 l0 = __float2bfloat16(v.x - __bfloat162float(h0));
                __nv_bfloat16 l1 = __float2bfloat16(v.y - __bfloat162float(h1));
                __nv_bfloat16 l2 = __float2bfloat16(v.z - __bfloat162float(h2));
                __nv_bfloat16 l3 = __float2bfloat16(v.w - __bfloat162float(h3));
                *(__nv_bfloat162*)&Ash[arow][kk]     = __halves2bfloat162(h0, h1);
                *(__nv_bfloat162*)&Ash[arow][kk + 2] = __halves2bfloat162(h2, h3);
                *(__nv_bfloat162*)&Asl[arow][kk]     = __halves2bfloat162(l0, l1);
                *(__nv_bfloat162*)&Asl[arow][kk + 2] = __halves2bfloat162(l2, l3);
            }
        }
        // ---- load B tiles (pre-split, n-major) ----
        {
            int n  = tid >> 1;
            int kb = (tid & 1) * 16;
            const uint4* bh = (const uint4*)&g_w1h[n * KPAD + k0 + kb];
            const uint4* bl = (const uint4*)&g_w1l[n * KPAD + k0 + kb];
            uint4 u0 = bh[0], u1 = bh[1];
            uint4 v0 = bl[0], v1 = bl[1];
            unsigned* dsth = (unsigned*)&Bsh[n][kb];
            unsigned* dstl = (unsigned*)&Bsl[n][kb];
            dsth[0] = u0.x; dsth[1] = u0.y; dsth[2] = u0.z; dsth[3] = u0.w;
            dsth[4] = u1.x; dsth[5] = u1.y; dsth[6] = u1.z; dsth[7] = u1.w;
            dstl[0] = v0.x; dstl[1] = v0.y; dstl[2] = v0.z; dstl[3] = v0.w;
            dstl[4] = v1.x; dstl[5] = v1.y; dstl[6] = v1.z; dstl[7] = v1.w;
        }
        __syncthreads();
        // ---- MMA over the 32-k tile (two k16 steps) ----
#pragma unroll
        for (int kk = 0; kk < 32; kk += 16) {
            unsigned ah[2][4], al[2][4];
#pragma unroll
            for (int mt = 0; mt < 2; mt++) {
                int rb = wm * 32 + mt * 16;
                ah[mt][0] = *(const unsigned*)&Ash[rb + gr][kk + q2];
                ah[mt][1] = *(const unsigned*)&Ash[rb + gr + 8][kk + q2];
                ah[mt][2] = *(const unsigned*)&Ash[rb + gr][kk + q2 + 8];
                ah[mt][3] = *(const unsigned*)&Ash[rb + gr + 8][kk + q2 + 8];
                al[mt][0] = *(const unsigned*)&Asl[rb + gr][kk + q2];
                al[mt][1] = *(const unsigned*)&Asl[rb + gr + 8][kk + q2];
                al[mt][2] = *(const unsigned*)&Asl[rb + gr][kk + q2 + 8];
                al[mt][3] = *(const unsigned*)&Asl[rb + gr + 8][kk + q2 + 8];
            }
#pragma unroll
            for (int nt = 0; nt < 8; nt++) {
                int nb = wn * 64 + nt * 8 + gr;
                unsigned bh0 = *(const unsigned*)&Bsh[nb][kk + q2];
                unsigned bh1 = *(const unsigned*)&Bsh[nb][kk + q2 + 8];
                unsigned bl0 = *(const unsigned*)&Bsl[nb][kk + q2];
                unsigned bl1 = *(const unsigned*)&Bsl[nb][kk + q2 + 8];
#pragma unroll
                for (int mt = 0; mt < 2; mt++) {
                    mma16816(d[mt][nt], ah[mt], bh0, bh1);
                    mma16816(d[mt][nt], ah[mt], bl0, bl1);
                    mma16816(d[mt][nt], al[mt], bh0, bh1);
                }
            }
        }
        __syncthreads();
    }
    // ---- store h1 ----
    float* out = (float*)g_h1v;
#pragma unroll
    for (int mt = 0; mt < 2; mt++) {
#pragma unroll
        for (int nt = 0; nt < 8; nt++) {
            int r0 = rowBase + wm * 32 + mt * 16 + gr;
            int c  = wn * 64 + nt * 8 + q2;
            if (r0 < NND) {
                float2 v0 = make_float2(d[mt][nt][0], d[mt][nt][1]);
                *(float2*)&out[(long)r0 * HC + c] = v0;
            }
            int r1 = r0 + 8;
            if (r1 < NND) {
                float2 v1 = make_float2(d[mt][nt][2], d[mt][nt][3]);
                *(float2*)&out[(long)r1 * HC + c] = v1;
            }
        }
    }
    // ---- fused att1: per-(row, head) dots with att_src/att_dst ----
    // thread's cols for head group hh (0..3): nt = 2*hh, 2*hh+1; global head = wn*4+hh
#pragma unroll
    for (int mt = 0; mt < 2; mt++) {
#pragma unroll
        for (int hh = 0; hh < 4; hh++) {
            float s0 = 0.f, d0 = 0.f, s1 = 0.f, d1 = 0.f;
#pragma unroll
            for (int t = 0; t < 2; t++) {
                int nt = hh * 2 + t;
                int c  = wn * 64 + nt * 8 + q2;
#pragma unroll
                for (int j = 0; j < 2; j++) {
                    float ws = att_s[c + j], wdv = att_d[c + j];
                    s0 += d[mt][nt][j]     * ws;
                    d0 += d[mt][nt][j]     * wdv;
                    s1 += d[mt][nt][2 + j] * ws;
                    d1 += d[mt][nt][2 + j] * wdv;
                }
            }
            // reduce over the 4-lane column group (lane&3)
#pragma unroll
            for (int m = 1; m <= 2; m <<= 1) {
                s0 += __shfl_xor_sync(0xFFFFFFFFu, s0, m);
                d0 += __shfl_xor_sync(0xFFFFFFFFu, d0, m);
                s1 += __shfl_xor_sync(0xFFFFFFFFu, s1, m);
                d1 += __shfl_xor_sync(0xFFFFFFFFu, d1, m);
            }
            if ((lane & 3) == 0) {
                int h  = wn * 4 + hh;
                int r0 = rowBase + wm * 32 + mt * 16 + gr;
                int r1 = r0 + 8;
                if (r0 < NND) { g_asrc1[r0 * H1 + h] = s0; g_adst1[r0 * H1 + h] = d0; }
                if (r1 < NND) { g_asrc1[r1 * H1 + h] = s1; g_adst1[r1 * H1 + h] = d1; }
            }
        }
    }
}

// ---------------- layer-1 aggregation + fused layer-2 projection ----------
// warp per dst node; lane covers one float4 (4 channels), head = lane>>2
__global__ __launch_bounds__(256) void k_agg1(const float* __restrict__ b1,
                                              const float* __restrict__ W2,
                                              const float* __restrict__ as2,
                                              const float* __restrict__ ad2) {
    __shared__ float W2s[HC * NCLS];
    const int tid = threadIdx.x;
#pragma unroll
    for (int i = 0; i < 4; i++) {
        int idx = tid + i * 256;
        if (idx < HC * NCLS) W2s[idx] = W2[idx];
    }
    __syncthreads();

    int warp = (blockIdx.x * blockDim.x + tid) >> 5;
    int lane = tid & 31;
    if (warp >= NND) return;
    const int n = warp;
    const int head = lane >> 2;

    const float ad = g_adst1[n * H1 + head];
    const int beg = g_offs[n];
    const int deg = g_deg[n];

    float4 acc = make_float4(0.f, 0.f, 0.f, 0.f);
    float den = 0.f;
    int t = 0;
    for (; t + 2 <= deg; t += 2) {
        int s0 = g_csrc[beg + t];
        int s1 = g_csrc[beg + t + 1];
        float e0 = g_asrc1[s0 * H1 + head] + ad;
        float e1 = g_asrc1[s1 * H1 + head] + ad;
        float4 h0 = g_h1v[s0 * HCV + lane];
        float4 h1 = g_h1v[s1 * HCV + lane];
        e0 = (e0 > 0.f) ? e0 : NEG * e0;
        e1 = (e1 > 0.f) ? e1 : NEG * e1;
        float w0 = __expf(e0);
        float w1 = __expf(e1);
        acc.x += w0 * h0.x + w1 * h1.x;
        acc.y += w0 * h0.y + w1 * h1.y;
        acc.z += w0 * h0.z + w1 * h1.z;
        acc.w += w0 * h0.w + w1 * h1.w;
        den += w0 + w1;
    }
    if (t < deg) {
        int s0 = g_csrc[beg + t];
        float e0 = g_asrc1[s0 * H1 + head] + ad;
        float4 h0 = g_h1v[s0 * HCV + lane];
        e0 = (e0 > 0.f) ? e0 : NEG * e0;
        float w0 = __expf(e0);
        acc.x += w0 * h0.x; acc.y += w0 * h0.y;
        acc.z += w0 * h0.z; acc.w += w0 * h0.w;
        den += w0;
    }
    float inv = 1.f / (den + 1e-16f);
    float o[4];
    o[0] = fmaxf(acc.x * inv + b1[lane * 4 + 0], 0.f);
    o[1] = fmaxf(acc.y * inv + b1[lane * 4 + 1], 0.f);
    o[2] = fmaxf(acc.z * inv + b1[lane * 4 + 2], 0.f);
    o[3] = fmaxf(acc.w * inv + b1[lane * 4 + 3], 0.f);

    // fused proj2: h2 row (registers across warp) x W2 [128,7]
    float pa[NCLS];
#pragma unroll
    for (int c = 0; c < NCLS; c++) pa[c] = 0.f;
#pragma unroll
    for (int j = 0; j < 4; j++) {
        const float* wrow = &W2s[(lane * 4 + j) * NCLS];
#pragma unroll
        for (int c = 0; c < NCLS; c++) pa[c] += o[j] * wrow[c];
    }
#pragma unroll
    for (int c = 0; c < NCLS; c++) {
#pragma unroll
        for (int off = 16; off > 0; off >>= 1)
            pa[c] += __shfl_down_sync(0xFFFFFFFFu, pa[c], off);
    }
    if (lane == 0) {
        float s = 0.f, d2 = 0.f;
#pragma unroll
        for (int c = 0; c < NCLS; c++) {
            g_p2[n * NCLS + c] = pa[c];
            s  += pa[c] * as2[c];
            d2 += pa[c] * ad2[c];
        }
        g_a2s[n] = s;
        g_a2d[n] = d2;
    }
}

// ---------------- layer-2 aggregation -> output ----------------
__global__ __launch_bounds__(256) void k_agg2(const float* __restrict__ b2,
                                              float* __restrict__ out) {
    int t = blockIdx.x * blockDim.x + threadIdx.x;
    int n = t >> 3;
    int c = t & 7;
    if (n >= NND) return;

    const float ad = g_a2d[n];
    const int beg = g_offs[n];
    const int deg = g_deg[n];
    float acc = 0.f, den = 0.f;
    int i = 0;
    for (; i + 2 <= deg; i += 2) {
        int s0 = g_csrc[beg + i];
        int s1 = g_csrc[beg + i + 1];
        float e0 = g_a2s[s0] + ad;
        float e1 = g_a2s[s1] + ad;
        float p0 = (c < NCLS) ? g_p2[s0 * NCLS + c] : 0.f;
        float p1 = (c < NCLS) ? g_p2[s1 * NCLS + c] : 0.f;
        e0 = (e0 > 0.f) ? e0 : NEG * e0;
        e1 = (e1 > 0.f) ? e1 : NEG * e1;
        float w0 = __expf(e0);
        float w1 = __expf(e1);
        den += w0 + w1;
        acc += w0 * p0 + w1 * p1;
    }
    if (i < deg) {
        int s0 = g_csrc[beg + i];
        float e0 = g_a2s[s0] + ad;
        float p0 = (c < NCLS) ? g_p2[s0 * NCLS + c] : 0.f;
        e0 = (e0 > 0.f) ? e0 : NEG * e0;
        float w0 = __expf(e0);
        den += w0;
        acc += w0 * p0;
    }
    if (c < NCLS) out[n * NCLS + c] = acc / (den + 1e-16f) + b2[c];
}

// ---------------- launch ----------------
extern "C" void kernel_launch(void* const* d_in, const int* in_sizes, int n_in,
                              void* d_out, int out_size) {
    const float* x   = (const float*)d_in[0];
    const void*  ei  = d_in[1];
    const float* W1  = (const float*)d_in[2];
    const float* as1 = (const float*)d_in[3];
    const float* ad1 = (const float*)d_in[4];
    const float* b1  = (const float*)d_in[5];
    const float* W2  = (const float*)d_in[6];
    const float* as2 = (const float*)d_in[7];
    const float* ad2 = (const float*)d_in[8];
    const float* b2  = (const float*)d_in[9];
    float* out = (float*)d_out;

    k_setup<<<1 + NBLK + PREPB, 256>>>((const unsigned int*)ei, W1);  // 1
    k_hist<<<(NET + 255) / 256, 256>>>(ei);                           // 2
    k_scanA<<<NBLK, 256>>>();                                         // 3
    k_gemm1<<<(NND + 127) / 128, 256>>>(x, as1, ad1);                 // 4 (profiled)
    k_scanB<<<1, 256>>>();                                            // 5
    k_scanC<<<NBLK, 256>>>();                                         // 6
    k_scatter<<<(NET + 255) / 256, 256>>>(ei);                        // 7
    k_agg1<<<(NND * 32 + 255) / 256, 256>>>(b1, W2, as2, ad2);        // 8
    k_agg2<<<(NND * 8 + 255) / 256, 256>>>(b2, out);                  // 9
}

// round 16
// speedup vs baseline: 2.8348x; 1.2666x over previous
#include <cuda_runtime.h>
#include <cuda_bf16.h>

// Problem constants (fixed shapes)
#define NND   50000
#define NE    800000
#define NET   850000      // E + N self loops
#define FIN   500
#define KPAD  512         // FIN padded for MMA k-tiling
#define H1    8
#define C1    16
#define HC    128         // H1*C1
#define HCV   32          // HC/4 float4s per node
#define NCLS  7
#define NEG   0.2f
#define NBLK  196         // ceil(NND/256) scan blocks
#define PREPB 256         // prepw blocks (65536/256)

// GEMM pipeline geometry
#define ASTRIDE 36                      // fp32 per A smem row (144B, 16B-mult)
#define BSTRIDE 40                      // bf16 per B smem row (80B, 16B-mult, conflict-free)
#define ABYTES  (128 * ASTRIDE * 4)     // 18432
#define BBYTES  (128 * BSTRIDE * 2)     // 10240
#define STAGEB  (ABYTES + 2 * BBYTES)   // 38912
#define SMEMTOT (2 * STAGEB)            // 77824

// ---------------- scratch (static device globals; no allocs) ----------------
__device__ float4 g_h1v[NND * HCV];    // layer1 features h = x@W1 (vec4)
__device__ float  g_asrc1[NND * H1];
__device__ float  g_adst1[NND * H1];
__device__ float  g_p2[NND * NCLS];    // layer2 projected
__device__ float  g_a2s[NND];
__device__ float  g_a2d[NND];
__device__ int    g_deg[NND];
__device__ int    g_offs[NND];
__device__ int    g_cur[NND];
__device__ int    g_part[NBLK];        // per-block degree partial sums
__device__ int    g_poff[NBLK];        // scanned partials
__device__ int    g_csrc[NET];         // CSR: sources of incoming edges per dst
__device__ int    g_is64;              // 1 if edge_index is int64, 0 if int32
__device__ __nv_bfloat16 g_w1h[HC * KPAD];  // W1^T bf16 hi  [n][k]
__device__ __nv_bfloat16 g_w1l[HC * KPAD];  // W1^T bf16 lo  [n][k]

__device__ __forceinline__ int load_edge(const void* ei, long long idx) {
    if (g_is64) return (int)((const long long*)ei)[idx];
    return ((const int*)ei)[idx];
}

// ---------------- setup: dtype detect + zero degrees + W1 split ------------
__global__ __launch_bounds__(256) void k_setup(const unsigned int* __restrict__ w,
                                               const float* __restrict__ W1) {
    int b = blockIdx.x;
    if (b == 0) {
        __shared__ unsigned int s[256];
        unsigned int v = 0;
        for (int i = threadIdx.x; i < 8192; i += 256) v |= w[2 * i + 1];
        s[threadIdx.x] = v;
        __syncthreads();
        for (int off = 128; off > 0; off >>= 1) {
            if (threadIdx.x < off) s[threadIdx.x] |= s[threadIdx.x + off];
            __syncthreads();
        }
        if (threadIdx.x == 0) g_is64 = (s[0] == 0u) ? 1 : 0;
    } else if (b < 1 + NBLK) {
        int i = (b - 1) * 256 + threadIdx.x;
        if (i < NND) g_deg[i] = 0;
    } else {
        int idx = (b - 1 - NBLK) * 256 + threadIdx.x;   // 0..65535
        if (idx < HC * KPAD) {
            int n = idx >> 9, k = idx & (KPAD - 1);
            float v = (k < FIN) ? W1[k * HC + n] : 0.f;
            __nv_bfloat16 h = __float2bfloat16(v);
            float lo = v - __bfloat162float(h);
            g_w1h[idx] = h;
            g_w1l[idx] = __float2bfloat16(lo);
        }
    }
}

// ---------------- CSR build ----------------
__global__ __launch_bounds__(256) void k_hist(const void* __restrict__ ei) {
    int e = blockIdx.x * blockDim.x + threadIdx.x;
    if (e >= NET) return;
    int dst = (e < NE) ? load_edge(ei, (long long)NE + e) : (e - NE);
    if ((unsigned)dst < NND) atomicAdd(&g_deg[dst], 1);
}

__global__ __launch_bounds__(256) void k_scanA() {
    __shared__ int s[256];
    int i = blockIdx.x * 256 + threadIdx.x;
    s[threadIdx.x] = (i < NND) ? g_deg[i] : 0;
    __syncthreads();
    for (int off = 128; off > 0; off >>= 1) {
        if (threadIdx.x < off) s[threadIdx.x] += s[threadIdx.x + off];
        __syncthreads();
    }
    if (threadIdx.x == 0) g_part[blockIdx.x] = s[0];
}

__global__ __launch_bounds__(256) void k_scanB() {
    __shared__ int s[256];
    int t = threadIdx.x;
    int v = (t < NBLK) ? g_part[t] : 0;
    s[t] = v;
    __syncthreads();
    for (int off = 1; off < 256; off <<= 1) {
        int u = 0;
        if (t >= off) u = s[t - off];
        __syncthreads();
        s[t] += u;
        __syncthreads();
    }
    if (t < NBLK) g_poff[t] = s[t] - v;   // exclusive
}

__global__ __launch_bounds__(256) void k_scanC() {
    __shared__ int s[256];
    int t = threadIdx.x;
    int i = blockIdx.x * 256 + t;
    int v = (i < NND) ? g_deg[i] : 0;
    s[t] = v;
    __syncthreads();
    for (int off = 1; off < 256; off <<= 1) {
        int u = 0;
        if (t >= off) u = s[t - off];
        __syncthreads();
        s[t] += u;
        __syncthreads();
    }
    if (i < NND) {
        int o = g_poff[blockIdx.x] + s[t] - v;
        g_offs[i] = o;
        g_cur[i]  = o;
    }
}

__global__ __launch_bounds__(256) void k_scatter(const void* __restrict__ ei) {
    int e = blockIdx.x * blockDim.x + threadIdx.x;
    if (e >= NET) return;
    int src, dst;
    if (e < NE) {
        src = load_edge(ei, e);
        dst = load_edge(ei, (long long)NE + e);
    } else {
        src = e - NE; dst = e - NE;
    }
    if ((unsigned)dst >= NND || (unsigned)src >= NND) return;
    int pos = atomicAdd(&g_cur[dst], 1);
    if ((unsigned)pos < NET) g_csrc[pos] = src;
}

// ---------------- GEMM1 (tensor cores, cp.async pipelined) + fused att1 ----
__device__ __forceinline__ void mma16816(float* d, const unsigned* a,
                                         unsigned b0, unsigned b1) {
    asm volatile(
        "mma.sync.aligned.m16n8k16.row.col.f32.bf16.bf16.f32 "
        "{%0,%1,%2,%3}, {%4,%5,%6,%7}, {%8,%9}, {%0,%1,%2,%3};"
        : "+f"(d[0]), "+f"(d[1]), "+f"(d[2]), "+f"(d[3])
        : "r"(a[0]), "r"(a[1]), "r"(a[2]), "r"(a[3]), "r"(b0), "r"(b1));
}

__device__ __forceinline__ void cpa16(void* dst, const void* src, int srcsz) {
    unsigned sdst = (unsigned)__cvta_generic_to_shared(dst);
    asm volatile("cp.async.ca.shared.global [%0], [%1], 16, %2;"
                 :: "r"(sdst), "l"(src), "r"(srcsz));
}

// fp32 pair -> bf16x2 hi + bf16x2 lo (3-term split building block)
__device__ __forceinline__ void split2(float2 v, unsigned& h, unsigned& l) {
    asm("cvt.rn.bf16x2.f32 %0, %1, %2;" : "=r"(h) : "f"(v.y), "f"(v.x));
    float hx = __uint_as_float(h << 16);
    float hy = __uint_as_float(h & 0xffff0000u);
    float lx = v.x - hx;
    float ly = v.y - hy;
    asm("cvt.rn.bf16x2.f32 %0, %1, %2;" : "=r"(l) : "f"(ly), "f"(lx));
}

__global__ __launch_bounds__(256, 2) void k_gemm1(const float* __restrict__ x,
                                                  const float* __restrict__ as1,
                                                  const float* __restrict__ ad1) {
    extern __shared__ char dynsmem[];
    __shared__ float att_s[HC], att_d[HC];

    const int tid  = threadIdx.x;
    const int lane = tid & 31;
    const int wid  = tid >> 5;
    const int wm   = wid & 3;        // m-warp: rows wm*32
    const int wn   = wid >> 2;       // n-warp: cols wn*64
    const int gr   = lane >> 2;      // 0..7
    const int q2   = (lane & 3) * 2; // 0,2,4,6
    const int rowBase = blockIdx.x * 128;

    if (tid < HC) { att_s[tid] = as1[tid]; att_d[tid] = ad1[tid]; }

    float d[2][8][4];
#pragma unroll
    for (int a = 0; a < 2; a++)
#pragma unroll
        for (int b = 0; b < 8; b++)
#pragma unroll
            for (int c = 0; c < 4; c++) d[a][b][c] = 0.f;

    // ---- stage issue: A fp32 (zero-filled pad) + B bf16 hi/lo ----
    auto issue_stage = [&](int s, int k0) {
        char* base = dynsmem + s * STAGEB;
        float* A32 = (float*)base;
        __nv_bfloat16* Bh = (__nv_bfloat16*)(base + ABYTES);
        __nv_bfloat16* Bl = (__nv_bfloat16*)(base + ABYTES + BBYTES);
        // A: 1024 16B ops (128 rows x 8 chunks of 4 floats)
#pragma unroll
        for (int t = 0; t < 4; t++) {
            int j = tid + t * 256;
            int row = j >> 3, chunk = j & 7;
            int r = rowBase + row;
            int k = k0 + chunk * 4;
            int sz = (r < NND && k < FIN) ? 16 : 0;
            int rc = (r < NND) ? r : (NND - 1);
            int kc = (k < FIN) ? k : 0;
            cpa16(A32 + row * ASTRIDE + chunk * 4,
                  x + (long)rc * FIN + kc, sz);
        }
        // B hi: 512 ops (128 n x 4 chunks of 8 bf16)
#pragma unroll
        for (int t = 0; t < 2; t++) {
            int j = tid + t * 256;
            int n = j >> 2, chunk = j & 3;
            cpa16(Bh + n * BSTRIDE + chunk * 8,
                  g_w1h + n * KPAD + k0 + chunk * 8, 16);
        }
        // B lo
#pragma unroll
        for (int t = 0; t < 2; t++) {
            int j = tid + t * 256;
            int n = j >> 2, chunk = j & 3;
            cpa16(Bl + n * BSTRIDE + chunk * 8,
                  g_w1l + n * KPAD + k0 + chunk * 8, 16);
        }
    };

    issue_stage(0, 0);
    asm volatile("cp.async.commit_group;");

    for (int i = 0; i < KPAD / 32; i++) {
        if (i + 1 < KPAD / 32) issue_stage((i + 1) & 1, (i + 1) * 32);
        asm volatile("cp.async.commit_group;");
        asm volatile("cp.async.wait_group 1;");
        __syncthreads();

        char* base = dynsmem + (i & 1) * STAGEB;
        float* A32 = (float*)base;
        __nv_bfloat16* Bh = (__nv_bfloat16*)(base + ABYTES);
        __nv_bfloat16* Bl = (__nv_bfloat16*)(base + ABYTES + BBYTES);

#pragma unroll
        for (int kk = 0; kk < 32; kk += 16) {
            unsigned ah[2][4], al[2][4];
#pragma unroll
            for (int mt = 0; mt < 2; mt++) {
                int rb = wm * 32 + mt * 16;
                float2 v0 = *(const float2*)&A32[(rb + gr)     * ASTRIDE + kk + q2];
                float2 v1 = *(const float2*)&A32[(rb + gr + 8) * ASTRIDE + kk + q2];
                float2 v2 = *(const float2*)&A32[(rb + gr)     * ASTRIDE + kk + q2 + 8];
                float2 v3 = *(const float2*)&A32[(rb + gr + 8) * ASTRIDE + kk + q2 + 8];
                split2(v0, ah[mt][0], al[mt][0]);
                split2(v1, ah[mt][1], al[mt][1]);
                split2(v2, ah[mt][2], al[mt][2]);
                split2(v3, ah[mt][3], al[mt][3]);
            }
#pragma unroll
            for (int nt = 0; nt < 8; nt++) {
                int nb = wn * 64 + nt * 8 + gr;
                unsigned bh0 = *(const unsigned*)&Bh[nb * BSTRIDE + kk + q2];
                unsigned bh1 = *(const unsigned*)&Bh[nb * BSTRIDE + kk + q2 + 8];
                unsigned bl0 = *(const unsigned*)&Bl[nb * BSTRIDE + kk + q2];
                unsigned bl1 = *(const unsigned*)&Bl[nb * BSTRIDE + kk + q2 + 8];
#pragma unroll
                for (int mt = 0; mt < 2; mt++) {
                    mma16816(d[mt][nt], ah[mt], bh0, bh1);
                    mma16816(d[mt][nt], ah[mt], bl0, bl1);
                    mma16816(d[mt][nt], al[mt], bh0, bh1);
                }
            }
        }
        __syncthreads();
    }

    // ---- store h1 ----
    float* out = (float*)g_h1v;
#pragma unroll
    for (int mt = 0; mt < 2; mt++) {
#pragma unroll
        for (int nt = 0; nt < 8; nt++) {
            int r0 = rowBase + wm * 32 + mt * 16 + gr;
            int c  = wn * 64 + nt * 8 + q2;
            if (r0 < NND) {
                float2 v0 = make_float2(d[mt][nt][0], d[mt][nt][1]);
                *(float2*)&out[(long)r0 * HC + c] = v0;
            }
            int r1 = r0 + 8;
            if (r1 < NND) {
                float2 v1 = make_float2(d[mt][nt][2], d[mt][nt][3]);
                *(float2*)&out[(long)r1 * HC + c] = v1;
            }
        }
    }
    // ---- fused att1: per-(row, head) dots with att_src/att_dst ----
#pragma unroll
    for (int mt = 0; mt < 2; mt++) {
#pragma unroll
        for (int hh = 0; hh < 4; hh++) {
            float s0 = 0.f, d0 = 0.f, s1 = 0.f, d1 = 0.f;
#pragma unroll
            for (int t = 0; t < 2; t++) {
                int nt = hh * 2 + t;
                int c  = wn * 64 + nt * 8 + q2;
#pragma unroll
                for (int j = 0; j < 2; j++) {
                    float ws = att_s[c + j], wdv = att_d[c + j];
                    s0 += d[mt][nt][j]     * ws;
                    d0 += d[mt][nt][j]     * wdv;
                    s1 += d[mt][nt][2 + j] * ws;
                    d1 += d[mt][nt][2 + j] * wdv;
                }
            }
#pragma unroll
            for (int m = 1; m <= 2; m <<= 1) {
                s0 += __shfl_xor_sync(0xFFFFFFFFu, s0, m);
                d0 += __shfl_xor_sync(0xFFFFFFFFu, d0, m);
                s1 += __shfl_xor_sync(0xFFFFFFFFu, s1, m);
                d1 += __shfl_xor_sync(0xFFFFFFFFu, d1, m);
            }
            if ((lane & 3) == 0) {
                int h  = wn * 4 + hh;
                int r0 = rowBase + wm * 32 + mt * 16 + gr;
                int r1 = r0 + 8;
                if (r0 < NND) { g_asrc1[r0 * H1 + h] = s0; g_adst1[r0 * H1 + h] = d0; }
                if (r1 < NND) { g_asrc1[r1 * H1 + h] = s1; g_adst1[r1 * H1 + h] = d1; }
            }
        }
    }
}

// ---------------- layer-1 aggregation + fused layer-2 projection ----------
__global__ __launch_bounds__(256) void k_agg1(const float* __restrict__ b1,
                                              const float* __restrict__ W2,
                                              const float* __restrict__ as2,
                                              const float* __restrict__ ad2) {
    __shared__ float W2s[HC * NCLS];
    const int tid = threadIdx.x;
#pragma unroll
    for (int i = 0; i < 4; i++) {
        int idx = tid + i * 256;
        if (idx < HC * NCLS) W2s[idx] = W2[idx];
    }
    __syncthreads();

    int warp = (blockIdx.x * blockDim.x + tid) >> 5;
    int lane = tid & 31;
    if (warp >= NND) return;
    const int n = warp;
    const int head = lane >> 2;

    const float ad = g_adst1[n * H1 + head];
    const int beg = g_offs[n];
    const int deg = g_deg[n];

    float4 acc = make_float4(0.f, 0.f, 0.f, 0.f);
    float den = 0.f;
    int t = 0;
    for (; t + 2 <= deg; t += 2) {
        int s0 = g_csrc[beg + t];
        int s1 = g_csrc[beg + t + 1];
        float e0 = g_asrc1[s0 * H1 + head] + ad;
        float e1 = g_asrc1[s1 * H1 + head] + ad;
        float4 h0 = g_h1v[s0 * HCV + lane];
        float4 h1 = g_h1v[s1 * HCV + lane];
        e0 = (e0 > 0.f) ? e0 : NEG * e0;
        e1 = (e1 > 0.f) ? e1 : NEG * e1;
        float w0 = __expf(e0);
        float w1 = __expf(e1);
        acc.x += w0 * h0.x + w1 * h1.x;
        acc.y += w0 * h0.y + w1 * h1.y;
        acc.z += w0 * h0.z + w1 * h1.z;
        acc.w += w0 * h0.w + w1 * h1.w;
        den += w0 + w1;
    }
    if (t < deg) {
        int s0 = g_csrc[beg + t];
        float e0 = g_asrc1[s0 * H1 + head] + ad;
        float4 h0 = g_h1v[s0 * HCV + lane];
        e0 = (e0 > 0.f) ? e0 : NEG * e0;
        float w0 = __expf(e0);
        acc.x += w0 * h0.x; acc.y += w0 * h0.y;
        acc.z += w0 * h0.z; acc.w += w0 * h0.w;
        den += w0;
    }
    float inv = 1.f / (den + 1e-16f);
    float o[4];
    o[0] = fmaxf(acc.x * inv + b1[lane * 4 + 0], 0.f);
    o[1] = fmaxf(acc.y * inv + b1[lane * 4 + 1], 0.f);
    o[2] = fmaxf(acc.z * inv + b1[lane * 4 + 2], 0.f);
    o[3] = fmaxf(acc.w * inv + b1[lane * 4 + 3], 0.f);

    // fused proj2
    float pa[NCLS];
#pragma unroll
    for (int c = 0; c < NCLS; c++) pa[c] = 0.f;
#pragma unroll
    for (int j = 0; j < 4; j++) {
        const float* wrow = &W2s[(lane * 4 + j) * NCLS];
#pragma unroll
        for (int c = 0; c < NCLS; c++) pa[c] += o[j] * wrow[c];
    }
#pragma unroll
    for (int c = 0; c < NCLS; c++) {
#pragma unroll
        for (int off = 16; off > 0; off >>= 1)
            pa[c] += __shfl_down_sync(0xFFFFFFFFu, pa[c], off);
    }
    if (lane == 0) {
        float s = 0.f, d2 = 0.f;
#pragma unroll
        for (int c = 0; c < NCLS; c++) {
            g_p2[n * NCLS + c] = pa[c];
            s  += pa[c] * as2[c];
            d2 += pa[c] * ad2[c];
        }
        g_a2s[n] = s;
        g_a2d[n] = d2;
    }
}

// ---------------- layer-2 aggregation -> output ----------------
__global__ __launch_bounds__(256) void k_agg2(const float* __restrict__ b2,
                                              float* __restrict__ out) {
    int t = blockIdx.x * blockDim.x + threadIdx.x;
    int n = t >> 3;
    int c = t & 7;
    if (n >= NND) return;

    const float ad = g_a2d[n];
    const int beg = g_offs[n];
    const int deg = g_deg[n];
    float acc = 0.f, den = 0.f;
    int i = 0;
    for (; i + 2 <= deg; i += 2) {
        int s0 = g_csrc[beg + i];
        int s1 = g_csrc[beg + i + 1];
        float e0 = g_a2s[s0] + ad;
        float e1 = g_a2s[s1] + ad;
        float p0 = (c < NCLS) ? g_p2[s0 * NCLS + c] : 0.f;
        float p1 = (c < NCLS) ? g_p2[s1 * NCLS + c] : 0.f;
        e0 = (e0 > 0.f) ? e0 : NEG * e0;
        e1 = (e1 > 0.f) ? e1 : NEG * e1;
        float w0 = __expf(e0);
        float w1 = __expf(e1);
        den += w0 + w1;
        acc += w0 * p0 + w1 * p1;
    }
    if (i < deg) {
        int s0 = g_csrc[beg + i];
        float e0 = g_a2s[s0] + ad;
        float p0 = (c < NCLS) ? g_p2[s0 * NCLS + c] : 0.f;
        e0 = (e0 > 0.f) ? e0 : NEG * e0;
        float w0 = __expf(e0);
        den += w0;
        acc += w0 * p0;
    }
    if (c < NCLS) out[n * NCLS + c] = acc / (den + 1e-16f) + b2[c];
}

// ---------------- launch ----------------
extern "C" void kernel_launch(void* const* d_in, const int* in_sizes, int n_in,
                              void* d_out, int out_size) {
    const float* x   = (const float*)d_in[0];
    const void*  ei  = d_in[1];
    const float* W1  = (const float*)d_in[2];
    const float* as1 = (const float*)d_in[3];
    const float* ad1 = (const float*)d_in[4];
    const float* b1  = (const float*)d_in[5];
    const float* W2  = (const float*)d_in[6];
    const float* as2 = (const float*)d_in[7];
    const float* ad2 = (const float*)d_in[8];
    const float* b2  = (const float*)d_in[9];
    float* out = (float*)d_out;

    static int s_attr_done = 0;
    if (!s_attr_done) {
        cudaFuncSetAttribute(k_gemm1,
                             cudaFuncAttributeMaxDynamicSharedMemorySize, SMEMTOT);
        s_attr_done = 1;
    }

    k_setup<<<1 + NBLK + PREPB, 256>>>((const unsigned int*)ei, W1);  // 1
    k_hist<<<(NET + 255) / 256, 256>>>(ei);                           // 2
    k_scanA<<<NBLK, 256>>>();                                         // 3
    k_gemm1<<<(NND + 127) / 128, 256, SMEMTOT>>>(x, as1, ad1);        // 4 (profiled)
    k_scanB<<<1, 256>>>();                                            // 5
    k_scanC<<<NBLK, 256>>>();                                         // 6
    k_scatter<<<(NET + 255) / 256, 256>>>(ei);                        // 7
    k_agg1<<<(NND * 32 + 255) / 256, 256>>>(b1, W2, as2, ad2);        // 8
    k_agg2<<<(NND * 8 + 255) / 256, 256>>>(b2, out);                  // 9
}

// round 17
// speedup vs baseline: 3.2641x; 1.1515x over previous
#include <cuda_runtime.h>
#include <cuda_bf16.h>
#include <cuda_fp16.h>

// Problem constants (fixed shapes)
#define NND   50000
#define NE    800000
#define NET   850000      // E + N self loops
#define FIN   500
#define KPAD  512         // FIN padded for MMA k-tiling
#define H1    8
#define C1    16
#define HC    128         // H1*C1
#define NCLS  7
#define NEG   0.2f
#define NBLK  196         // ceil(NND/256) scan blocks
#define PREPB 256         // prepw blocks (65536/256)

// GEMM pipeline geometry
#define ASTRIDE 36                      // fp32 per A smem row (144B, 16B-mult)
#define BSTRIDE 40                      // bf16 per B smem row (80B, 16B-mult)
#define ABYTES  (128 * ASTRIDE * 4)     // 18432
#define BBYTES  (128 * BSTRIDE * 2)     // 10240
#define STAGEB  (ABYTES + 2 * BBYTES)   // 38912
#define SMEMTOT (2 * STAGEB)            // 77824

// ---------------- scratch (static device globals; no allocs) ----------------
__device__ __half g_h1h[NND * HC];     // layer1 features h = x@W1 (fp16)
__device__ float  g_asrc1[NND * H1];
__device__ float  g_adst1[NND * H1];
__device__ float  g_p2[NND * NCLS];    // layer2 projected
__device__ float  g_a2s[NND];
__device__ float  g_a2d[NND];
__device__ int    g_deg[NND];
__device__ int    g_offs[NND];
__device__ int    g_cur[NND];
__device__ int    g_part[NBLK];        // per-block degree partial sums
__device__ int    g_poff[NBLK];        // scanned partials
__device__ int    g_csrc[NET];         // CSR: sources of incoming edges per dst
__device__ int    g_is64;              // 1 if edge_index is int64, 0 if int32
__device__ __nv_bfloat16 g_w1h[HC * KPAD];  // W1^T bf16 hi  [n][k]
__device__ __nv_bfloat16 g_w1l[HC * KPAD];  // W1^T bf16 lo  [n][k]

__device__ __forceinline__ int load_edge(const void* ei, long long idx) {
    if (g_is64) return (int)((const long long*)ei)[idx];
    return ((const int*)ei)[idx];
}

// ---------------- setup: dtype detect + zero degrees + W1 split ------------
__global__ __launch_bounds__(256) void k_setup(const unsigned int* __restrict__ w,
                                               const float* __restrict__ W1) {
    int b = blockIdx.x;
    if (b == 0) {
        __shared__ unsigned int s[256];
        unsigned int v = 0;
        for (int i = threadIdx.x; i < 8192; i += 256) v |= w[2 * i + 1];
        s[threadIdx.x] = v;
        __syncthreads();
        for (int off = 128; off > 0; off >>= 1) {
            if (threadIdx.x < off) s[threadIdx.x] |= s[threadIdx.x + off];
            __syncthreads();
        }
        if (threadIdx.x == 0) g_is64 = (s[0] == 0u) ? 1 : 0;
    } else if (b < 1 + NBLK) {
        int i = (b - 1) * 256 + threadIdx.x;
        if (i < NND) g_deg[i] = 0;
    } else {
        int idx = (b - 1 - NBLK) * 256 + threadIdx.x;   // 0..65535
        if (idx < HC * KPAD) {
            int n = idx >> 9, k = idx & (KPAD - 1);
            float v = (k < FIN) ? W1[k * HC + n] : 0.f;
            __nv_bfloat16 h = __float2bfloat16(v);
            float lo = v - __bfloat162float(h);
            g_w1h[idx] = h;
            g_w1l[idx] = __float2bfloat16(lo);
        }
    }
}

// ---------------- CSR build ----------------
__global__ __launch_bounds__(256) void k_hist(const void* __restrict__ ei) {
    int e = blockIdx.x * blockDim.x + threadIdx.x;
    if (e >= NET) return;
    int dst = (e < NE) ? load_edge(ei, (long long)NE + e) : (e - NE);
    if ((unsigned)dst < NND) atomicAdd(&g_deg[dst], 1);
}

__global__ __launch_bounds__(256) void k_scanA() {
    __shared__ int s[256];
    int i = blockIdx.x * 256 + threadIdx.x;
    s[threadIdx.x] = (i < NND) ? g_deg[i] : 0;
    __syncthreads();
    for (int off = 128; off > 0; off >>= 1) {
        if (threadIdx.x < off) s[threadIdx.x] += s[threadIdx.x + off];
        __syncthreads();
    }
    if (threadIdx.x == 0) g_part[blockIdx.x] = s[0];
}

__global__ __launch_bounds__(256) void k_scanB() {
    __shared__ int s[256];
    int t = threadIdx.x;
    int v = (t < NBLK) ? g_part[t] : 0;
    s[t] = v;
    __syncthreads();
    for (int off = 1; off < 256; off <<= 1) {
        int u = 0;
        if (t >= off) u = s[t - off];
        __syncthreads();
        s[t] += u;
        __syncthreads();
    }
    if (t < NBLK) g_poff[t] = s[t] - v;   // exclusive
}

__global__ __launch_bounds__(256) void k_scanC() {
    __shared__ int s[256];
    int t = threadIdx.x;
    int i = blockIdx.x * 256 + t;
    int v = (i < NND) ? g_deg[i] : 0;
    s[t] = v;
    __syncthreads();
    for (int off = 1; off < 256; off <<= 1) {
        int u = 0;
        if (t >= off) u = s[t - off];
        __syncthreads();
        s[t] += u;
        __syncthreads();
    }
    if (i < NND) {
        int o = g_poff[blockIdx.x] + s[t] - v;
        g_offs[i] = o;
        g_cur[i]  = o;
    }
}

__global__ __launch_bounds__(256) void k_scatter(const void* __restrict__ ei) {
    int e = blockIdx.x * blockDim.x + threadIdx.x;
    if (e >= NET) return;
    int src, dst;
    if (e < NE) {
        src = load_edge(ei, e);
        dst = load_edge(ei, (long long)NE + e);
    } else {
        src = e - NE; dst = e - NE;
    }
    if ((unsigned)dst >= NND || (unsigned)src >= NND) return;
    int pos = atomicAdd(&g_cur[dst], 1);
    if ((unsigned)pos < NET) g_csrc[pos] = src;
}

// ---------------- GEMM1 (tensor cores, cp.async pipelined) + fused att1 ----
__device__ __forceinline__ void mma16816(float* d, const unsigned* a,
                                         unsigned b0, unsigned b1) {
    asm volatile(
        "mma.sync.aligned.m16n8k16.row.col.f32.bf16.bf16.f32 "
        "{%0,%1,%2,%3}, {%4,%5,%6,%7}, {%8,%9}, {%0,%1,%2,%3};"
        : "+f"(d[0]), "+f"(d[1]), "+f"(d[2]), "+f"(d[3])
        : "r"(a[0]), "r"(a[1]), "r"(a[2]), "r"(a[3]), "r"(b0), "r"(b1));
}

__device__ __forceinline__ void cpa16(void* dst, const void* src, int srcsz) {
    unsigned sdst = (unsigned)__cvta_generic_to_shared(dst);
    asm volatile("cp.async.ca.shared.global [%0], [%1], 16, %2;"
                 :: "r"(sdst), "l"(src), "r"(srcsz));
}

// fp32 pair -> bf16x2 hi + bf16x2 lo (3-term split building block)
__device__ __forceinline__ void split2(float2 v, unsigned& h, unsigned& l) {
    asm("cvt.rn.bf16x2.f32 %0, %1, %2;" : "=r"(h) : "f"(v.y), "f"(v.x));
    float hx = __uint_as_float(h << 16);
    float hy = __uint_as_float(h & 0xffff0000u);
    float lx = v.x - hx;
    float ly = v.y - hy;
    asm("cvt.rn.bf16x2.f32 %0, %1, %2;" : "=r"(l) : "f"(ly), "f"(lx));
}

__global__ __launch_bounds__(256, 2) void k_gemm1(const float* __restrict__ x,
                                                  const float* __restrict__ as1,
                                                  const float* __restrict__ ad1) {
    extern __shared__ char dynsmem[];
    __shared__ float att_s[HC], att_d[HC];

    const int tid  = threadIdx.x;
    const int lane = tid & 31;
    const int wid  = tid >> 5;
    const int wm   = wid & 3;        // m-warp: rows wm*32
    const int wn   = wid >> 2;       // n-warp: cols wn*64
    const int gr   = lane >> 2;      // 0..7
    const int q2   = (lane & 3) * 2; // 0,2,4,6
    const int rowBase = blockIdx.x * 128;

    if (tid < HC) { att_s[tid] = as1[tid]; att_d[tid] = ad1[tid]; }

    float d[2][8][4];
#pragma unroll
    for (int a = 0; a < 2; a++)
#pragma unroll
        for (int b = 0; b < 8; b++)
#pragma unroll
            for (int c = 0; c < 4; c++) d[a][b][c] = 0.f;

    auto issue_stage = [&](int s, int k0) {
        char* base = dynsmem + s * STAGEB;
        float* A32 = (float*)base;
        __nv_bfloat16* Bh = (__nv_bfloat16*)(base + ABYTES);
        __nv_bfloat16* Bl = (__nv_bfloat16*)(base + ABYTES + BBYTES);
#pragma unroll
        for (int t = 0; t < 4; t++) {
            int j = tid + t * 256;
            int row = j >> 3, chunk = j & 7;
            int r = rowBase + row;
            int k = k0 + chunk * 4;
            int sz = (r < NND && k < FIN) ? 16 : 0;
            int rc = (r < NND) ? r : (NND - 1);
            int kc = (k < FIN) ? k : 0;
            cpa16(A32 + row * ASTRIDE + chunk * 4,
                  x + (long)rc * FIN + kc, sz);
        }
#pragma unroll
        for (int t = 0; t < 2; t++) {
            int j = tid + t * 256;
            int n = j >> 2, chunk = j & 3;
            cpa16(Bh + n * BSTRIDE + chunk * 8,
                  g_w1h + n * KPAD + k0 + chunk * 8, 16);
        }
#pragma unroll
        for (int t = 0; t < 2; t++) {
            int j = tid + t * 256;
            int n = j >> 2, chunk = j & 3;
            cpa16(Bl + n * BSTRIDE + chunk * 8,
                  g_w1l + n * KPAD + k0 + chunk * 8, 16);
        }
    };

    issue_stage(0, 0);
    asm volatile("cp.async.commit_group;");

    for (int i = 0; i < KPAD / 32; i++) {
        if (i + 1 < KPAD / 32) issue_stage((i + 1) & 1, (i + 1) * 32);
        asm volatile("cp.async.commit_group;");
        asm volatile("cp.async.wait_group 1;");
        __syncthreads();

        char* base = dynsmem + (i & 1) * STAGEB;
        float* A32 = (float*)base;
        __nv_bfloat16* Bh = (__nv_bfloat16*)(base + ABYTES);
        __nv_bfloat16* Bl = (__nv_bfloat16*)(base + ABYTES + BBYTES);

#pragma unroll
        for (int kk = 0; kk < 32; kk += 16) {
            unsigned ah[2][4], al[2][4];
#pragma unroll
            for (int mt = 0; mt < 2; mt++) {
                int rb = wm * 32 + mt * 16;
                float2 v0 = *(const float2*)&A32[(rb + gr)     * ASTRIDE + kk + q2];
                float2 v1 = *(const float2*)&A32[(rb + gr + 8) * ASTRIDE + kk + q2];
                float2 v2 = *(const float2*)&A32[(rb + gr)     * ASTRIDE + kk + q2 + 8];
                float2 v3 = *(const float2*)&A32[(rb + gr + 8) * ASTRIDE + kk + q2 + 8];
                split2(v0, ah[mt][0], al[mt][0]);
                split2(v1, ah[mt][1], al[mt][1]);
                split2(v2, ah[mt][2], al[mt][2]);
                split2(v3, ah[mt][3], al[mt][3]);
            }
#pragma unroll
            for (int nt = 0; nt < 8; nt++) {
                int nb = wn * 64 + nt * 8 + gr;
                unsigned bh0 = *(const unsigned*)&Bh[nb * BSTRIDE + kk + q2];
                unsigned bh1 = *(const unsigned*)&Bh[nb * BSTRIDE + kk + q2 + 8];
                unsigned bl0 = *(const unsigned*)&Bl[nb * BSTRIDE + kk + q2];
                unsigned bl1 = *(const unsigned*)&Bl[nb * BSTRIDE + kk + q2 + 8];
#pragma unroll
                for (int mt = 0; mt < 2; mt++) {
                    mma16816(d[mt][nt], ah[mt], bh0, bh1);
                    mma16816(d[mt][nt], ah[mt], bl0, bl1);
                    mma16816(d[mt][nt], al[mt], bh0, bh1);
                }
            }
        }
        __syncthreads();
    }

    // ---- store h1 (fp16) ----
#pragma unroll
    for (int mt = 0; mt < 2; mt++) {
#pragma unroll
        for (int nt = 0; nt < 8; nt++) {
            int r0 = rowBase + wm * 32 + mt * 16 + gr;
            int c  = wn * 64 + nt * 8 + q2;
            if (r0 < NND) {
                *(__half2*)&g_h1h[(size_t)r0 * HC + c] =
                    __floats2half2_rn(d[mt][nt][0], d[mt][nt][1]);
            }
            int r1 = r0 + 8;
            if (r1 < NND) {
                *(__half2*)&g_h1h[(size_t)r1 * HC + c] =
                    __floats2half2_rn(d[mt][nt][2], d[mt][nt][3]);
            }
        }
    }
    // ---- fused att1 (fp32 accumulators, exact) ----
#pragma unroll
    for (int mt = 0; mt < 2; mt++) {
#pragma unroll
        for (int hh = 0; hh < 4; hh++) {
            float s0 = 0.f, d0 = 0.f, s1 = 0.f, d1 = 0.f;
#pragma unroll
            for (int t = 0; t < 2; t++) {
                int nt = hh * 2 + t;
                int c  = wn * 64 + nt * 8 + q2;
#pragma unroll
                for (int j = 0; j < 2; j++) {
                    float ws = att_s[c + j], wdv = att_d[c + j];
                    s0 += d[mt][nt][j]     * ws;
                    d0 += d[mt][nt][j]     * wdv;
                    s1 += d[mt][nt][2 + j] * ws;
                    d1 += d[mt][nt][2 + j] * wdv;
                }
            }
#pragma unroll
            for (int m = 1; m <= 2; m <<= 1) {
                s0 += __shfl_xor_sync(0xFFFFFFFFu, s0, m);
                d0 += __shfl_xor_sync(0xFFFFFFFFu, d0, m);
                s1 += __shfl_xor_sync(0xFFFFFFFFu, s1, m);
                d1 += __shfl_xor_sync(0xFFFFFFFFu, d1, m);
            }
            if ((lane & 3) == 0) {
                int h  = wn * 4 + hh;
                int r0 = rowBase + wm * 32 + mt * 16 + gr;
                int r1 = r0 + 8;
                if (r0 < NND) { g_asrc1[r0 * H1 + h] = s0; g_adst1[r0 * H1 + h] = d0; }
                if (r1 < NND) { g_asrc1[r1 * H1 + h] = s1; g_adst1[r1 * H1 + h] = d1; }
            }
        }
    }
}

// ---------------- layer-1 aggregation + fused layer-2 projection ----------
__global__ __launch_bounds__(256) void k_agg1(const float* __restrict__ b1,
                                              const float* __restrict__ W2,
                                              const float* __restrict__ as2,
                                              const float* __restrict__ ad2) {
    __shared__ float W2s[HC * NCLS];
    const int tid = threadIdx.x;
#pragma unroll
    for (int i = 0; i < 4; i++) {
        int idx = tid + i * 256;
        if (idx < HC * NCLS) W2s[idx] = W2[idx];
    }
    __syncthreads();

    int warp = (blockIdx.x * blockDim.x + tid) >> 5;
    int lane = tid & 31;
    if (warp >= NND) return;
    const int n = warp;
    const int head = lane >> 2;

    const float ad = g_adst1[n * H1 + head];
    const int beg = g_offs[n];
    const int deg = g_deg[n];

    float4 acc = make_float4(0.f, 0.f, 0.f, 0.f);
    float den = 0.f;
    int t = 0;
    for (; t + 2 <= deg; t += 2) {
        int s0 = g_csrc[beg + t];
        int s1 = g_csrc[beg + t + 1];
        float e0 = g_asrc1[s0 * H1 + head] + ad;
        float e1 = g_asrc1[s1 * H1 + head] + ad;
        uint2 u0 = *(const uint2*)&g_h1h[(size_t)s0 * HC + lane * 4];
        uint2 u1 = *(const uint2*)&g_h1h[(size_t)s1 * HC + lane * 4];
        e0 = (e0 > 0.f) ? e0 : NEG * e0;
        e1 = (e1 > 0.f) ? e1 : NEG * e1;
        float w0 = __expf(e0);
        float w1 = __expf(e1);
        float2 a01 = __half22float2(*(__half2*)&u0.x);
        float2 a23 = __half22float2(*(__half2*)&u0.y);
        float2 b01 = __half22float2(*(__half2*)&u1.x);
        float2 b23 = __half22float2(*(__half2*)&u1.y);
        acc.x += w0 * a01.x + w1 * b01.x;
        acc.y += w0 * a01.y + w1 * b01.y;
        acc.z += w0 * a23.x + w1 * b23.x;
        acc.w += w0 * a23.y + w1 * b23.y;
        den += w0 + w1;
    }
    if (t < deg) {
        int s0 = g_csrc[beg + t];
        float e0 = g_asrc1[s0 * H1 + head] + ad;
        uint2 u0 = *(const uint2*)&g_h1h[(size_t)s0 * HC + lane * 4];
        e0 = (e0 > 0.f) ? e0 : NEG * e0;
        float w0 = __expf(e0);
        float2 a01 = __half22float2(*(__half2*)&u0.x);
        float2 a23 = __half22float2(*(__half2*)&u0.y);
        acc.x += w0 * a01.x; acc.y += w0 * a01.y;
        acc.z += w0 * a23.x; acc.w += w0 * a23.y;
        den += w0;
    }
    float inv = 1.f / (den + 1e-16f);
    float o[4];
    o[0] = fmaxf(acc.x * inv + b1[lane * 4 + 0], 0.f);
    o[1] = fmaxf(acc.y * inv + b1[lane * 4 + 1], 0.f);
    o[2] = fmaxf(acc.z * inv + b1[lane * 4 + 2], 0.f);
    o[3] = fmaxf(acc.w * inv + b1[lane * 4 + 3], 0.f);

    // fused proj2
    float pa[NCLS];
#pragma unroll
    for (int c = 0; c < NCLS; c++) pa[c] = 0.f;
#pragma unroll
    for (int j = 0; j < 4; j++) {
        const float* wrow = &W2s[(lane * 4 + j) * NCLS];
#pragma unroll
        for (int c = 0; c < NCLS; c++) pa[c] += o[j] * wrow[c];
    }
#pragma unroll
    for (int c = 0; c < NCLS; c++) {
#pragma unroll
        for (int off = 16; off > 0; off >>= 1)
            pa[c] += __shfl_down_sync(0xFFFFFFFFu, pa[c], off);
    }
    if (lane == 0) {
        float s = 0.f, d2 = 0.f;
#pragma unroll
        for (int c = 0; c < NCLS; c++) {
            g_p2[n * NCLS + c] = pa[c];
            s  += pa[c] * as2[c];
            d2 += pa[c] * ad2[c];
        }
        g_a2s[n] = s;
        g_a2d[n] = d2;
    }
}

// ---------------- layer-2 aggregation -> output ----------------
__global__ __launch_bounds__(256) void k_agg2(const float* __restrict__ b2,
                                              float* __restrict__ out) {
    int t = blockIdx.x * blockDim.x + threadIdx.x;
    int n = t >> 3;
    int c = t & 7;
    if (n >= NND) return;

    const float ad = g_a2d[n];
    const int beg = g_offs[n];
    const int deg = g_deg[n];
    float acc = 0.f, den = 0.f;
    int i = 0;
    for (; i + 2 <= deg; i += 2) {
        int s0 = g_csrc[beg + i];
        int s1 = g_csrc[beg + i + 1];
        float e0 = g_a2s[s0] + ad;
        float e1 = g_a2s[s1] + ad;
        float p0 = (c < NCLS) ? g_p2[s0 * NCLS + c] : 0.f;
        float p1 = (c < NCLS) ? g_p2[s1 * NCLS + c] : 0.f;
        e0 = (e0 > 0.f) ? e0 : NEG * e0;
        e1 = (e1 > 0.f) ? e1 : NEG * e1;
        float w0 = __expf(e0);
        float w1 = __expf(e1);
        den += w0 + w1;
        acc += w0 * p0 + w1 * p1;
    }
    if (i < deg) {
        int s0 = g_csrc[beg + i];
        float e0 = g_a2s[s0] + ad;
        float p0 = (c < NCLS) ? g_p2[s0 * NCLS + c] : 0.f;
        e0 = (e0 > 0.f) ? e0 : NEG * e0;
        float w0 = __expf(e0);
        den += w0;
        acc += w0 * p0;
    }
    if (c < NCLS) out[n * NCLS + c] = acc / (den + 1e-16f) + b2[c];
}

// ---------------- launch ----------------
extern "C" void kernel_launch(void* const* d_in, const int* in_sizes, int n_in,
                              void* d_out, int out_size) {
    const float* x   = (const float*)d_in[0];
    const void*  ei  = d_in[1];
    const float* W1  = (const float*)d_in[2];
    const float* as1 = (const float*)d_in[3];
    const float* ad1 = (const float*)d_in[4];
    const float* b1  = (const float*)d_in[5];
    const float* W2  = (const float*)d_in[6];
    const float* as2 = (const float*)d_in[7];
    const float* ad2 = (const float*)d_in[8];
    const float* b2  = (const float*)d_in[9];
    float* out = (float*)d_out;

    // one-time resources (created on the first, non-capturing call)
    static cudaStream_t s2 = nullptr;
    static cudaEvent_t evFork = nullptr, evJoin = nullptr;
    if (s2 == nullptr) {
        cudaStreamCreateWithFlags(&s2, cudaStreamNonBlocking);
        cudaEventCreateWithFlags(&evFork, cudaEventDisableTiming);
        cudaEventCreateWithFlags(&evJoin, cudaEventDisableTiming);
        cudaFuncSetAttribute(k_gemm1,
                             cudaFuncAttributeMaxDynamicSharedMemorySize, SMEMTOT);
    }

    // setup on main stream
    k_setup<<<1 + NBLK + PREPB, 256>>>((const unsigned int*)ei, W1);

    // fork: CSR chain on s2, concurrent with gemm1 on main stream
    cudaEventRecord(evFork, 0);
    cudaStreamWaitEvent(s2, evFork, 0);
    k_hist<<<(NET + 255) / 256, 256, 0, s2>>>(ei);
    k_scanA<<<NBLK, 256, 0, s2>>>();
    k_scanB<<<1, 256, 0, s2>>>();
    k_scanC<<<NBLK, 256, 0, s2>>>();
    k_scatter<<<(NET + 255) / 256, 256, 0, s2>>>(ei);
    cudaEventRecord(evJoin, s2);

    k_gemm1<<<(NND + 127) / 128, 256, SMEMTOT>>>(x, as1, ad1);

    // join, then aggregation chain on main stream
    cudaStreamWaitEvent(0, evJoin, 0);
    k_agg1<<<(NND * 32 + 255) / 256, 256>>>(b1, W2, as2, ad2);
    k_agg2<<<(NND * 8 + 255) / 256, 256>>>(b2, out);
}